// round 2
// baseline (speedup 1.0000x reference)
#include <cuda_runtime.h>
#include <stdint.h>

#define MR   4096      // B*S rows
#define DD   768       // D
#define FF   12288     // F
#define TK   64        // top-k
#define NNZ_MAX (1 << 22)
#define SMEM_TOPK (FF*4 + 256*4 + 8*4 + 512*4)

// ---------------- device scratch (static; no runtime allocation) -------------
__device__ float g_buf[(size_t)MR * FF];          // up_pre, then approx (reused)
__device__ float g_WdecUpT[(size_t)FF * DD];      // W_dec_up^T  [F,D]
__device__ float g_WdecDnT[(size_t)FF * DD];      // W_dec_down^T [F,D]
__device__ float g_add1[FF];                      // b_enc_up - W_enc_up @ b_dec_up
__device__ float g_add2[FF];                      // b_enc_down + W_enc_down @ b_dec_up
__device__ int   g_colcnt[FF];
__device__ int   g_colfill[FF];
__device__ int   g_colptr[FF + 1];
__device__ int   g_rowidx[NNZ_MAX];
__device__ float g_mval[NNZ_MAX];
__device__ float g_upval[MR * TK];
__device__ int   g_upidx[MR * TK];
__device__ float g_dnval[MR * TK];
__device__ int   g_dnidx[MR * TK];
__device__ int   g_isb;                           // mask is byte-packed?

// ---------------- helpers ----------------------------------------------------
__device__ __forceinline__ unsigned f2k(float f) {
    unsigned u = __float_as_uint(f);
    return (u & 0x80000000u) ? ~u : (u | 0x80000000u);
}
__device__ __forceinline__ float k2f(unsigned u) {
    return __uint_as_float((u & 0x80000000u) ? (u ^ 0x80000000u) : ~u);
}

// ---------------- init + mask format detection -------------------------------
__global__ void k_init() {
    int i = blockIdx.x * blockDim.x + threadIdx.x;
    if (i < FF) { g_colcnt[i] = 0; g_colfill[i] = 0; }
    if (i == 0) g_isb = 0;
}

// Scan first 16MB of mask as dwords. Byte-packed bool mask: some dword > 1
// with every byte in {0,1}. int32/float32 masks never produce that pattern.
__global__ void k_detect(const unsigned* __restrict__ m) {
    unsigned gid = blockIdx.x * blockDim.x + threadIdx.x;  // 262144 threads
    bool isb = false;
#pragma unroll
    for (int t = 0; t < 16; t++) {
        unsigned v = m[gid + (unsigned)t * 262144u];
        bool bytes01 = ((v & 0xFEFEFEFEu) == 0u);
        isb |= (v > 1u) && bytes01;
    }
    if (__ballot_sync(0xFFFFFFFFu, isb) && (threadIdx.x & 31) == 0)
        atomicOr(&g_isb, 1);
}

// ---------------- transpose [DD, FF] -> [FF, DD] ------------------------------
__global__ void k_transpose(const float* __restrict__ in, int which) {
    __shared__ float t[32][33];
    float* out = which ? g_WdecDnT : g_WdecUpT;
    int bf = blockIdx.x * 32, bd = blockIdx.y * 32;
    int x = threadIdx.x, y = threadIdx.y;
#pragma unroll
    for (int r = 0; r < 32; r += 8)
        t[y + r][x] = in[(size_t)(bd + y + r) * FF + bf + x];
    __syncthreads();
#pragma unroll
    for (int r = 0; r < 32; r += 8)
        out[(size_t)(bf + y + r) * DD + bd + x] = t[x][y + r];
}

// ---------------- bias vectors: one warp per feature -------------------------
__global__ void k_addvec(const float* __restrict__ Weu, const float* __restrict__ beu,
                         const float* __restrict__ bdu, const float* __restrict__ Wed,
                         const float* __restrict__ bed) {
    int warp = threadIdx.x >> 5, lane = threadIdx.x & 31;
    int n = blockIdx.x * 8 + warp;
    const float* r1 = Weu + (size_t)n * DD;
    const float* r2 = Wed + (size_t)n * DD;
    float s1 = 0.f, s2 = 0.f;
#pragma unroll
    for (int t = 0; t < 6; t++) {
        int off = lane * 4 + t * 128;
        float4 bv = *(const float4*)(bdu + off);
        float4 w1 = *(const float4*)(r1 + off);
        float4 w2 = *(const float4*)(r2 + off);
        s1 += bv.x * w1.x + bv.y * w1.y + bv.z * w1.z + bv.w * w1.w;
        s2 += bv.x * w2.x + bv.y * w2.y + bv.z * w2.z + bv.w * w2.w;
    }
#pragma unroll
    for (int o = 16; o; o >>= 1) {
        s1 += __shfl_xor_sync(0xFFFFFFFFu, s1, o);
        s2 += __shfl_xor_sync(0xFFFFFFFFu, s2, o);
    }
    if (lane == 0) {
        g_add1[n] = beu[n] - s1;
        g_add2[n] = bed[n] + s2;
    }
}

// ---------------- CSC build of masked virtual matrix -------------------------
__global__ void k_maskcount(const void* __restrict__ maskp) {
    int fd = blockIdx.x;
    if (g_isb) {
        const unsigned* row = (const unsigned*)maskp + (size_t)fd * (FF / 4);
        for (int w = threadIdx.x; w < FF / 4; w += blockDim.x) {
            unsigned v = row[w];
            if (v) {
#pragma unroll
                for (int b = 0; b < 4; b++)
                    if ((v >> (8 * b)) & 0xFFu) atomicAdd(&g_colcnt[w * 4 + b], 1);
            }
        }
    } else {
        const unsigned* row = (const unsigned*)maskp + (size_t)fd * FF;
        for (int j = threadIdx.x; j < FF; j += blockDim.x)
            if (row[j]) atomicAdd(&g_colcnt[j], 1);
    }
}

__global__ void k_scan() {  // single block, 1024 threads, 12 cols/thread
    __shared__ int partial[1024];
    int tid = threadIdx.x;
    int base = tid * 12;
    int loc[12];
    int s = 0;
#pragma unroll
    for (int t = 0; t < 12; t++) { loc[t] = s; s += g_colcnt[base + t]; }
    partial[tid] = s;
    __syncthreads();
    for (int off = 1; off < 1024; off <<= 1) {
        int v = (tid >= off) ? partial[tid - off] : 0;
        __syncthreads();
        partial[tid] += v;
        __syncthreads();
    }
    int excl = (tid == 0) ? 0 : partial[tid - 1];
#pragma unroll
    for (int t = 0; t < 12; t++) g_colptr[base + t] = excl + loc[t];
    if (tid == 1023) g_colptr[FF] = partial[1023];
}

__global__ void k_maskfill(const void* __restrict__ maskp) {
    int fd = blockIdx.x;
    if (g_isb) {
        const unsigned* row = (const unsigned*)maskp + (size_t)fd * (FF / 4);
        for (int w = threadIdx.x; w < FF / 4; w += blockDim.x) {
            unsigned v = row[w];
            if (v) {
#pragma unroll
                for (int b = 0; b < 4; b++)
                    if ((v >> (8 * b)) & 0xFFu) {
                        int j = w * 4 + b;
                        int pos = g_colptr[j] + atomicAdd(&g_colfill[j], 1);
                        if (pos < NNZ_MAX) g_rowidx[pos] = fd;
                    }
            }
        }
    } else {
        const unsigned* row = (const unsigned*)maskp + (size_t)fd * FF;
        for (int j = threadIdx.x; j < FF; j += blockDim.x)
            if (row[j]) {
                int pos = g_colptr[j] + atomicAdd(&g_colfill[j], 1);
                if (pos < NNZ_MAX) g_rowidx[pos] = fd;
            }
    }
}

// SDDMM: mval[e] = dot(W_enc_down[fd,:], W_dec_up[:,j]) for each mask nonzero.
__global__ void k_mval(const float* __restrict__ Wed) {
    __shared__ float swd[DD];
    int j = blockIdx.x;
    const float* wdrow = g_WdecUpT + (size_t)j * DD;
    for (int i = threadIdx.x; i < DD; i += blockDim.x) swd[i] = wdrow[i];
    __syncthreads();
    int e0 = g_colptr[j];
    int e1 = g_colptr[j + 1];
    if (e1 > NNZ_MAX) e1 = NNZ_MAX;
    int warp = threadIdx.x >> 5, lane = threadIdx.x & 31;
    for (int e = e0 + warp; e < e1; e += (int)blockDim.x / 32) {
        int fd = g_rowidx[e];
        const float* wr = Wed + (size_t)fd * DD;
        float s = 0.f;
#pragma unroll
        for (int t = 0; t < 6; t++) {
            int off = lane * 4 + t * 128;
            float4 a = *(const float4*)(wr + off);
            float4 b = *(const float4*)(swd + off);
            s += a.x * b.x + a.y * b.y + a.z * b.z + a.w * b.w;
        }
#pragma unroll
        for (int o = 16; o; o >>= 1) s += __shfl_xor_sync(0xFFFFFFFFu, s, o);
        if (lane == 0) g_mval[e] = s;
    }
}

// ---------------- fp32 SGEMM (NT): g_buf = A[MR,DD] * B[FF,DD]^T + addv ------
__global__ void __launch_bounds__(256, 2)
k_gemm(const float* __restrict__ A, const float* __restrict__ B,
       int addsel, int do_relu) {
    __shared__ float As[2][16][132];
    __shared__ float Bs[2][16][132];
    const int tid = threadIdx.x;
    const int bm = blockIdx.y * 128;
    const int bn = blockIdx.x * 128;
    const int tx = tid & 15, ty = tid >> 4;
    const int lrow = tid >> 2;
    const int lcol = (tid & 3) << 2;
    const float* Ap = A + (size_t)(bm + lrow) * DD + lcol;
    const float* Bp = B + (size_t)(bn + lrow) * DD + lcol;

    float acc[8][8];
#pragma unroll
    for (int i = 0; i < 8; i++)
#pragma unroll
        for (int j = 0; j < 8; j++) acc[i][j] = 0.f;

    float4 a0 = *(const float4*)Ap;
    float4 a1 = *(const float4*)(Ap + 64 * DD);
    float4 b0 = *(const float4*)Bp;
    float4 b1 = *(const float4*)(Bp + 64 * DD);
    As[0][lcol + 0][lrow] = a0.x; As[0][lcol + 1][lrow] = a0.y;
    As[0][lcol + 2][lrow] = a0.z; As[0][lcol + 3][lrow] = a0.w;
    As[0][lcol + 0][lrow + 64] = a1.x; As[0][lcol + 1][lrow + 64] = a1.y;
    As[0][lcol + 2][lrow + 64] = a1.z; As[0][lcol + 3][lrow + 64] = a1.w;
    Bs[0][lcol + 0][lrow] = b0.x; Bs[0][lcol + 1][lrow] = b0.y;
    Bs[0][lcol + 2][lrow] = b0.z; Bs[0][lcol + 3][lrow] = b0.w;
    Bs[0][lcol + 0][lrow + 64] = b1.x; Bs[0][lcol + 1][lrow + 64] = b1.y;
    Bs[0][lcol + 2][lrow + 64] = b1.z; Bs[0][lcol + 3][lrow + 64] = b1.w;
    __syncthreads();

    int buf = 0;
    for (int k0 = 16; k0 <= DD; k0 += 16) {
        bool has_next = (k0 < DD);
        if (has_next) {
            a0 = *(const float4*)(Ap + k0);
            a1 = *(const float4*)(Ap + k0 + 64 * DD);
            b0 = *(const float4*)(Bp + k0);
            b1 = *(const float4*)(Bp + k0 + 64 * DD);
        }
#pragma unroll
        for (int kk = 0; kk < 16; kk++) {
            float4 t0 = *(const float4*)(&As[buf][kk][ty * 8]);
            float4 t1 = *(const float4*)(&As[buf][kk][ty * 8 + 4]);
            float4 u0 = *(const float4*)(&Bs[buf][kk][tx * 8]);
            float4 u1 = *(const float4*)(&Bs[buf][kk][tx * 8 + 4]);
            float ar[8] = {t0.x, t0.y, t0.z, t0.w, t1.x, t1.y, t1.z, t1.w};
            float br[8] = {u0.x, u0.y, u0.z, u0.w, u1.x, u1.y, u1.z, u1.w};
#pragma unroll
            for (int i = 0; i < 8; i++)
#pragma unroll
                for (int j = 0; j < 8; j++) acc[i][j] += ar[i] * br[j];
        }
        if (has_next) {
            int nb = buf ^ 1;
            As[nb][lcol + 0][lrow] = a0.x; As[nb][lcol + 1][lrow] = a0.y;
            As[nb][lcol + 2][lrow] = a0.z; As[nb][lcol + 3][lrow] = a0.w;
            As[nb][lcol + 0][lrow + 64] = a1.x; As[nb][lcol + 1][lrow + 64] = a1.y;
            As[nb][lcol + 2][lrow + 64] = a1.z; As[nb][lcol + 3][lrow + 64] = a1.w;
            Bs[nb][lcol + 0][lrow] = b0.x; Bs[nb][lcol + 1][lrow] = b0.y;
            Bs[nb][lcol + 2][lrow] = b0.z; Bs[nb][lcol + 3][lrow] = b0.w;
            Bs[nb][lcol + 0][lrow + 64] = b1.x; Bs[nb][lcol + 1][lrow + 64] = b1.y;
            Bs[nb][lcol + 2][lrow + 64] = b1.z; Bs[nb][lcol + 3][lrow + 64] = b1.w;
            __syncthreads();
            buf = nb;
        }
    }

    const float* addv = addsel ? g_add2 : g_add1;
    float ad[8];
#pragma unroll
    for (int j = 0; j < 8; j++) ad[j] = addv[bn + tx * 8 + j];
#pragma unroll
    for (int i = 0; i < 8; i++) {
        int m = bm + ty * 8 + i;
        float* crow = g_buf + (size_t)m * FF + bn + tx * 8;
        float v[8];
#pragma unroll
        for (int j = 0; j < 8; j++) {
            v[j] = acc[i][j] + ad[j];
            if (do_relu) v[j] = fmaxf(v[j], 0.f);
        }
        float4 o0 = {v[0], v[1], v[2], v[3]};
        float4 o1 = {v[4], v[5], v[6], v[7]};
        *(float4*)crow = o0;
        *(float4*)(crow + 4) = o1;
    }
}

// ---------------- exact deterministic top-64 (512 threads, keys in shared) ---
__device__ void topk_select(unsigned* keys, int* hist, int* misc, int* scanbuf,
                            float* oval, int* oidx) {
    const int tid = threadIdx.x;  // blockDim == 512
    if (tid == 0) { misc[0] = 0; misc[1] = TK; }
    __syncthreads();
#pragma unroll
    for (int pass = 0; pass < 4; pass++) {
        int shift = 24 - 8 * pass;
        unsigned pm = (pass == 0) ? 0u : (0xFFFFFFFFu << (shift + 8));
        for (int i = tid; i < 256; i += 512) hist[i] = 0;
        __syncthreads();
        unsigned prefix = (unsigned)misc[0];
        for (int i = tid; i < FF; i += 512) {
            unsigned u = keys[i];
            if ((u & pm) == prefix) atomicAdd(&hist[(u >> shift) & 255], 1);
        }
        __syncthreads();
        if (tid == 0) {
            int krem = misc[1], cum = 0, t = 0;
            for (int b = 255; b >= 0; b--) {
                int h = hist[b];
                if (cum + h >= krem) { t = b; break; }
                cum += h;
            }
            misc[0] = (int)(((unsigned)misc[0]) | ((unsigned)t << shift));
            misc[1] = krem - cum;
        }
        __syncthreads();
    }
    unsigned T = (unsigned)misc[0];
    int neq = misc[1];
    int base = TK - neq;
    // index-ordered compaction: deterministic, ties -> smallest indices
    int seg0 = tid * (FF / 512), seg1 = seg0 + (FF / 512);
    int cg = 0, ce = 0;
    for (int i = seg0; i < seg1; i++) {
        unsigned u = keys[i];
        cg += (u > T);
        ce += (u == T);
    }
    scanbuf[tid] = (cg << 16) | ce;
    __syncthreads();
    for (int off = 1; off < 512; off <<= 1) {
        int v = (tid >= off) ? scanbuf[tid - off] : 0;
        __syncthreads();
        scanbuf[tid] += v;
        __syncthreads();
    }
    int excl = tid ? scanbuf[tid - 1] : 0;
    int og = excl >> 16, oe = excl & 0xFFFF;
    for (int i = seg0; i < seg1; i++) {
        unsigned u = keys[i];
        if (u > T) {
            oidx[og] = i; oval[og] = k2f(u); og++;
        } else if (u == T) {
            if (oe < neq) { oidx[base + oe] = i; oval[base + oe] = k2f(u); }
            oe++;
        }
    }
}

__global__ void k_topk_up() {
    extern __shared__ unsigned sm[];
    unsigned* keys = sm;
    int* hist = (int*)(sm + FF);
    int* misc = hist + 256;
    int* scanbuf = misc + 8;
    int row = blockIdx.x;
    const float* src = g_buf + (size_t)row * FF;
    for (int i = threadIdx.x; i < FF; i += 512) keys[i] = f2k(src[i]);
    __syncthreads();
    topk_select(keys, hist, misc, scanbuf, g_upval + row * TK, g_upidx + row * TK);
}

// approx row += sparse contribs (per-column-disjoint writes), then top-64.
__global__ void k_contrib_topk() {
    extern __shared__ unsigned sm[];
    float* sA = (float*)sm;
    int* hist = (int*)(sm + FF);
    int* misc = hist + 256;
    int* scanbuf = misc + 8;
    __shared__ int sj[TK];
    __shared__ float sv[TK];
    int row = blockIdx.x;
    const float* src = g_buf + (size_t)row * FF;
    for (int i = threadIdx.x; i < FF; i += 512) sA[i] = src[i];
    if (threadIdx.x < TK) {
        sj[threadIdx.x] = g_upidx[row * TK + threadIdx.x];
        sv[threadIdx.x] = g_upval[row * TK + threadIdx.x];
    }
    __syncthreads();
    for (int s = 0; s < TK; s++) {
        int j = sj[s];
        float v = sv[s];
        int e0 = g_colptr[j];
        int e1 = g_colptr[j + 1];
        if (e1 > NNZ_MAX) e1 = NNZ_MAX;
        for (int e = e0 + threadIdx.x; e < e1; e += 512)
            sA[g_rowidx[e]] += v * g_mval[e];  // distinct fd within a column
        __syncthreads();
    }
    unsigned* keys = sm;
    for (int i = threadIdx.x; i < FF; i += 512) {
        float f = sA[i];
        __syncthreads();  // noop-level safety: all reads before overwrite
        keys[i] = f2k(f);
    }
    __syncthreads();
    topk_select(keys, hist, misc, scanbuf, g_dnval + row * TK, g_dnidx + row * TK);
}

// ---------------- decode: recon = b_dec_down + sum dnval * W_dec_down[:,idx] --
__global__ void k_decode(const float* __restrict__ bdd, float* __restrict__ out) {
    __shared__ float vj[TK];
    __shared__ int ij[TK];
    int row = blockIdx.x;
    if (threadIdx.x < TK) {
        vj[threadIdx.x] = g_dnval[row * TK + threadIdx.x];
        ij[threadIdx.x] = g_dnidx[row * TK + threadIdx.x];
    }
    __syncthreads();
    int d = threadIdx.x;  // blockDim == 768
    float acc = bdd[d];
#pragma unroll 8
    for (int s = 0; s < TK; s++)
        acc += vj[s] * g_WdecDnT[(size_t)ij[s] * DD + d];
    out[(size_t)row * DD + d] = acc;
}

// ---------------- launch ------------------------------------------------------
extern "C" void kernel_launch(void* const* d_in, const int* in_sizes, int n_in,
                              void* d_out, int out_size) {
    const float* x_up      = (const float*)d_in[0];
    const float* x_resid   = (const float*)d_in[1];
    const float* W_enc_up  = (const float*)d_in[2];
    const float* b_enc_up  = (const float*)d_in[3];
    const float* b_dec_up  = (const float*)d_in[4];
    const float* W_dec_up  = (const float*)d_in[5];
    const float* W_enc_down= (const float*)d_in[6];
    const float* b_enc_down= (const float*)d_in[7];
    const float* b_dec_down= (const float*)d_in[8];
    const float* W_dec_down= (const float*)d_in[9];
    const void*  conn_mask = d_in[10];
    float* out = (float*)d_out;

    cudaFuncSetAttribute(k_topk_up, cudaFuncAttributeMaxDynamicSharedMemorySize, SMEM_TOPK);
    cudaFuncSetAttribute(k_contrib_topk, cudaFuncAttributeMaxDynamicSharedMemorySize, SMEM_TOPK);

    k_init<<<48, 256>>>();
    k_detect<<<1024, 256>>>((const unsigned*)conn_mask);
    k_transpose<<<dim3(384, 24), dim3(32, 8)>>>(W_dec_up, 0);
    k_transpose<<<dim3(384, 24), dim3(32, 8)>>>(W_dec_down, 1);
    k_addvec<<<1536, 256>>>(W_enc_up, b_enc_up, b_dec_up, W_enc_down, b_enc_down);
    k_maskcount<<<FF, 256>>>(conn_mask);
    k_scan<<<1, 1024>>>();
    k_maskfill<<<FF, 256>>>(conn_mask);
    k_mval<<<FF, 256>>>(W_enc_down);
    k_gemm<<<dim3(96, 32), 256>>>(x_up, W_enc_up, 0, 1);
    k_topk_up<<<MR, 512, SMEM_TOPK>>>();
    k_gemm<<<dim3(96, 32), 256>>>(x_resid, W_enc_down, 1, 0);
    k_contrib_topk<<<MR, 512, SMEM_TOPK>>>();
    k_decode<<<MR, 768>>>(b_dec_down, out);
}

// round 6
// speedup vs baseline: 1.6552x; 1.6552x over previous
#include <cuda_runtime.h>
#include <cuda_bf16.h>
#include <stdint.h>

#define MR   4096      // B*S rows
#define DD   768       // D
#define FF   12288     // F
#define TK   64        // top-k
#define NNZ_MAX (1 << 22)
#define CAP 320
#define MARGIN 0.05f
#define SMEM_REF (FF*4 + 256*4 + 8*4 + CAP*12)

// GEMM tiling (pure bf16, exact refinement later makes noise harmless)
#define KC 32
#define NCHUNK (DD / KC)          // 24
#define STAGES 3
#define LDSS 40                   // smem row stride in bf16 (80B, ldmatrix conflict-free)
#define TILE_B (128 * LDSS * 2)   // 10240 bytes per tile
#define STAGE_B (2 * TILE_B)      // A|B
#define GM_SMEM (STAGES * STAGE_B)

// ---------------- device scratch (static; no runtime allocation) -------------
__device__ float g_buf[(size_t)MR * FF];
__device__ float g_WdecUpT[(size_t)FF * DD];
__device__ float g_WdecDnT[(size_t)FF * DD];
__device__ float g_add1[FF];
__device__ float g_add2[FF];
__device__ int   g_colcnt[FF];
__device__ int   g_colfill[FF];
__device__ int   g_colptr[FF + 1];
__device__ int   g_rowidx[NNZ_MAX];
__device__ float g_mval[NNZ_MAX];
__device__ float g_upval[MR * TK];
__device__ int   g_upidx[MR * TK];
__device__ float g_dnval[MR * TK];
__device__ int   g_dnidx[MR * TK];
__device__ int   g_isb;
__device__ __nv_bfloat16 g_A1h[(size_t)MR * DD];
__device__ __nv_bfloat16 g_A2h[(size_t)MR * DD];
__device__ __nv_bfloat16 g_B1h[(size_t)FF * DD];
__device__ __nv_bfloat16 g_B2h[(size_t)FF * DD];

// ---------------- small helpers ----------------------------------------------
__device__ __forceinline__ unsigned f2k(float f) {
    unsigned u = __float_as_uint(f);
    return (u & 0x80000000u) ? ~u : (u | 0x80000000u);
}
__device__ __forceinline__ float k2f(unsigned u) {
    return __uint_as_float((u & 0x80000000u) ? (u ^ 0x80000000u) : ~u);
}
__device__ __forceinline__ uint32_t smem_u32(const void* p) {
    uint32_t a;
    asm("{ .reg .u64 t; cvta.to.shared.u64 t, %1; cvt.u32.u64 %0, t; }" : "=r"(a) : "l"(p));
    return a;
}
__device__ __forceinline__ uint32_t bf2u(__nv_bfloat162 h) {
    return *reinterpret_cast<uint32_t*>(&h);
}
__device__ __forceinline__ void cp16(uint32_t dst, const void* src) {
    asm volatile("cp.async.cg.shared.global [%0], [%1], 16;" :: "r"(dst), "l"(src));
}
__device__ __forceinline__ void ldm4(uint32_t* r, uint32_t a) {
    asm volatile("ldmatrix.sync.aligned.m8n8.x4.shared.b16 {%0,%1,%2,%3}, [%4];"
                 : "=r"(r[0]), "=r"(r[1]), "=r"(r[2]), "=r"(r[3]) : "r"(a));
}
__device__ __forceinline__ void mma_bf16(float* c, const uint32_t* a, const uint32_t* b) {
    asm volatile(
        "mma.sync.aligned.m16n8k16.row.col.f32.bf16.bf16.f32 "
        "{%0,%1,%2,%3}, {%4,%5,%6,%7}, {%8,%9}, {%0,%1,%2,%3};"
        : "+f"(c[0]), "+f"(c[1]), "+f"(c[2]), "+f"(c[3])
        : "r"(a[0]), "r"(a[1]), "r"(a[2]), "r"(a[3]), "r"(b[0]), "r"(b[1]));
}
__device__ __forceinline__ float warp_red(float s) {
#pragma unroll
    for (int o = 16; o; o >>= 1) s += __shfl_xor_sync(0xFFFFFFFFu, s, o);
    return s;
}

// ---------------- init + mask format detection -------------------------------
__global__ void k_init() {
    int i = blockIdx.x * blockDim.x + threadIdx.x;
    if (i < FF) { g_colcnt[i] = 0; g_colfill[i] = 0; }
    if (i == 0) g_isb = 0;
}

__global__ void k_detect(const unsigned* __restrict__ m) {
    unsigned gid = blockIdx.x * blockDim.x + threadIdx.x;
    bool isb = false;
#pragma unroll
    for (int t = 0; t < 16; t++) {
        unsigned v = m[gid + (unsigned)t * 262144u];
        bool bytes01 = ((v & 0xFEFEFEFEu) == 0u);
        isb |= (v > 1u) && bytes01;
    }
    if (__ballot_sync(0xFFFFFFFFu, isb) && (threadIdx.x & 31) == 0)
        atomicOr(&g_isb, 1);
}

// ---------------- fp32 -> bf16 conversion --------------------------------------
__global__ void k_cvt(const float* __restrict__ in, __nv_bfloat16* __restrict__ hi) {
    int i = blockIdx.x * blockDim.x + threadIdx.x;
    float4 v = ((const float4*)in)[i];
    __nv_bfloat162 h0 = __floats2bfloat162_rn(v.x, v.y);
    __nv_bfloat162 h1 = __floats2bfloat162_rn(v.z, v.w);
    ((uint2*)hi)[i] = make_uint2(bf2u(h0), bf2u(h1));
}

// ---------------- transpose [DD, FF] -> [FF, DD] ------------------------------
__global__ void k_transpose(const float* __restrict__ in, int which) {
    __shared__ float t[32][33];
    float* out = which ? g_WdecDnT : g_WdecUpT;
    int bf = blockIdx.x * 32, bd = blockIdx.y * 32;
    int x = threadIdx.x, y = threadIdx.y;
#pragma unroll
    for (int r = 0; r < 32; r += 8)
        t[y + r][x] = in[(size_t)(bd + y + r) * FF + bf + x];
    __syncthreads();
#pragma unroll
    for (int r = 0; r < 32; r += 8)
        out[(size_t)(bf + y + r) * DD + bd + x] = t[x][y + r];
}

// ---------------- bias vectors ------------------------------------------------
__global__ void k_addvec(const float* __restrict__ Weu, const float* __restrict__ beu,
                         const float* __restrict__ bdu, const float* __restrict__ Wed,
                         const float* __restrict__ bed) {
    int warp = threadIdx.x >> 5, lane = threadIdx.x & 31;
    int n = blockIdx.x * 8 + warp;
    const float* r1 = Weu + (size_t)n * DD;
    const float* r2 = Wed + (size_t)n * DD;
    float s1 = 0.f, s2 = 0.f;
#pragma unroll
    for (int t = 0; t < 6; t++) {
        int off = lane * 4 + t * 128;
        float4 bv = *(const float4*)(bdu + off);
        float4 w1 = *(const float4*)(r1 + off);
        float4 w2 = *(const float4*)(r2 + off);
        s1 += bv.x * w1.x + bv.y * w1.y + bv.z * w1.z + bv.w * w1.w;
        s2 += bv.x * w2.x + bv.y * w2.y + bv.z * w2.z + bv.w * w2.w;
    }
    s1 = warp_red(s1); s2 = warp_red(s2);
    if (lane == 0) {
        g_add1[n] = beu[n] - s1;
        g_add2[n] = bed[n] + s2;
    }
}

// ---------------- CSC build of masked virtual matrix -------------------------
__global__ void k_maskcount(const void* __restrict__ maskp) {
    int fd = blockIdx.x;
    if (g_isb) {
        const unsigned* row = (const unsigned*)maskp + (size_t)fd * (FF / 4);
        for (int w = threadIdx.x; w < FF / 4; w += blockDim.x) {
            unsigned v = row[w];
            if (v) {
#pragma unroll
                for (int b = 0; b < 4; b++)
                    if ((v >> (8 * b)) & 0xFFu) atomicAdd(&g_colcnt[w * 4 + b], 1);
            }
        }
    } else {
        const unsigned* row = (const unsigned*)maskp + (size_t)fd * FF;
        for (int j = threadIdx.x; j < FF; j += blockDim.x)
            if (row[j]) atomicAdd(&g_colcnt[j], 1);
    }
}

__global__ void k_scan() {
    __shared__ int partial[1024];
    int tid = threadIdx.x;
    int base = tid * 12;
    int loc[12];
    int s = 0;
#pragma unroll
    for (int t = 0; t < 12; t++) { loc[t] = s; s += g_colcnt[base + t]; }
    partial[tid] = s;
    __syncthreads();
    for (int off = 1; off < 1024; off <<= 1) {
        int v = (tid >= off) ? partial[tid - off] : 0;
        __syncthreads();
        partial[tid] += v;
        __syncthreads();
    }
    int excl = (tid == 0) ? 0 : partial[tid - 1];
#pragma unroll
    for (int t = 0; t < 12; t++) g_colptr[base + t] = excl + loc[t];
    if (tid == 1023) g_colptr[FF] = partial[1023];
}

__global__ void k_maskfill(const void* __restrict__ maskp) {
    int fd = blockIdx.x;
    if (g_isb) {
        const unsigned* row = (const unsigned*)maskp + (size_t)fd * (FF / 4);
        for (int w = threadIdx.x; w < FF / 4; w += blockDim.x) {
            unsigned v = row[w];
            if (v) {
#pragma unroll
                for (int b = 0; b < 4; b++)
                    if ((v >> (8 * b)) & 0xFFu) {
                        int j = w * 4 + b;
                        int pos = g_colptr[j] + atomicAdd(&g_colfill[j], 1);
                        if (pos < NNZ_MAX) g_rowidx[pos] = fd;
                    }
            }
        }
    } else {
        const unsigned* row = (const unsigned*)maskp + (size_t)fd * FF;
        for (int j = threadIdx.x; j < FF; j += blockDim.x)
            if (row[j]) {
                int pos = g_colptr[j] + atomicAdd(&g_colfill[j], 1);
                if (pos < NNZ_MAX) g_rowidx[pos] = fd;
            }
    }
}

// SDDMM for mask nonzeros
__global__ void k_mval(const float* __restrict__ Wed) {
    __shared__ float swd[DD];
    int j = blockIdx.x;
    const float* wdrow = g_WdecUpT + (size_t)j * DD;
    for (int i = threadIdx.x; i < DD; i += blockDim.x) swd[i] = wdrow[i];
    __syncthreads();
    int e0 = g_colptr[j];
    int e1 = g_colptr[j + 1];
    if (e1 > NNZ_MAX) e1 = NNZ_MAX;
    int warp = threadIdx.x >> 5, lane = threadIdx.x & 31;
    for (int e = e0 + warp; e < e1; e += (int)blockDim.x / 32) {
        int fd = g_rowidx[e];
        const float* wr = Wed + (size_t)fd * DD;
        float s = 0.f;
#pragma unroll
        for (int t = 0; t < 6; t++) {
            int off = lane * 4 + t * 128;
            float4 a = *(const float4*)(wr + off);
            float4 b = *(const float4*)(swd + off);
            s += a.x * b.x + a.y * b.y + a.z * b.z + a.w * b.w;
        }
        s = warp_red(s);
        if (lane == 0) g_mval[e] = s;
    }
}

// ---------------- bf16 HMMA GEMM (NT): g_buf = A*B^T + addv (approximate) -----
__global__ void __launch_bounds__(256, 1)
k_gemm_mma(const __nv_bfloat16* __restrict__ Ah, const __nv_bfloat16* __restrict__ Bh,
           int addsel, int do_relu) {
    extern __shared__ char smraw[];
    const uint32_t sbase = smem_u32(smraw);
    const int tid = threadIdx.x;
    const int wid = tid >> 5, lane = tid & 31;
    const int bm = blockIdx.y * 128, bn = blockIdx.x * 128;
    const int wm = (wid & 1) * 64, wn = (wid >> 1) * 32;

    const int rr = tid >> 2, q = tid & 3;
    const __nv_bfloat16* srcA = Ah + (size_t)(bm + rr) * DD + q * 8;
    const __nv_bfloat16* srcB = Bh + (size_t)(bn + rr) * DD + q * 8;
    const uint32_t dst0 = sbase + rr * (LDSS * 2) + q * 16;

    float acc[4][4][4];
#pragma unroll
    for (int i = 0; i < 4; i++)
#pragma unroll
        for (int j = 0; j < 4; j++)
#pragma unroll
            for (int k = 0; k < 4; k++) acc[i][j][k] = 0.f;

#pragma unroll
    for (int s = 0; s < STAGES; s++) {
        int k0 = s * KC;
        uint32_t db = dst0 + s * STAGE_B;
        cp16(db, srcA + k0);
        cp16(db + 64 * (LDSS * 2), srcA + k0 + (size_t)64 * DD);
        cp16(db + TILE_B, srcB + k0);
        cp16(db + TILE_B + 64 * (LDSS * 2), srcB + k0 + (size_t)64 * DD);
        asm volatile("cp.async.commit_group;" ::: "memory");
    }

#pragma unroll 1
    for (int c = 0; c < NCHUNK; c++) {
        asm volatile("cp.async.wait_group %0;" :: "n"(STAGES - 1) : "memory");
        __syncthreads();
        int st = c % STAGES;
        uint32_t sA = sbase + st * STAGE_B;
        uint32_t sB = sA + TILE_B;
#pragma unroll
        for (int kk = 0; kk < KC / 16; kk++) {
            uint32_t ah[4][4], bh[4][2];
            int arow = wm + (lane & 15);
            int acol = kk * 16 + (lane >> 4) * 8;
#pragma unroll
            for (int f = 0; f < 4; f++)
                ldm4(ah[f], sA + (uint32_t)((arow + f * 16) * LDSS + acol) * 2);
            int brow = wn + ((lane >> 4) << 3) + (lane & 7);
            int bcol = kk * 16 + ((lane >> 3) & 1) * 8;
#pragma unroll
            for (int g = 0; g < 2; g++) {
                uint32_t r4[4];
                ldm4(r4, sB + (uint32_t)((brow + g * 16) * LDSS + bcol) * 2);
                bh[g * 2][0] = r4[0]; bh[g * 2][1] = r4[1];
                bh[g * 2 + 1][0] = r4[2]; bh[g * 2 + 1][1] = r4[3];
            }
#pragma unroll
            for (int mi = 0; mi < 4; mi++)
#pragma unroll
                for (int ni = 0; ni < 4; ni++)
                    mma_bf16(acc[mi][ni], ah[mi], bh[ni]);
        }
        __syncthreads();
        if (c + STAGES < NCHUNK) {
            int k0 = (c + STAGES) * KC;
            uint32_t db = dst0 + st * STAGE_B;
            cp16(db, srcA + k0);
            cp16(db + 64 * (LDSS * 2), srcA + k0 + (size_t)64 * DD);
            cp16(db + TILE_B, srcB + k0);
            cp16(db + TILE_B + 64 * (LDSS * 2), srcB + k0 + (size_t)64 * DD);
        }
        asm volatile("cp.async.commit_group;" ::: "memory");
    }

    const float* addv = addsel ? g_add2 : g_add1;
#pragma unroll
    for (int ni = 0; ni < 4; ni++) {
        int col = bn + wn + ni * 8 + (lane & 3) * 2;
        float a0 = addv[col], a1 = addv[col + 1];
#pragma unroll
        for (int mi = 0; mi < 4; mi++) {
            int row = bm + wm + mi * 16 + (lane >> 2);
            float v0 = acc[mi][ni][0] + a0;
            float v1 = acc[mi][ni][1] + a1;
            float v2 = acc[mi][ni][2] + a0;
            float v3 = acc[mi][ni][3] + a1;
            if (do_relu) {
                v0 = fmaxf(v0, 0.f); v1 = fmaxf(v1, 0.f);
                v2 = fmaxf(v2, 0.f); v3 = fmaxf(v3, 0.f);
            }
            *(float2*)(g_buf + (size_t)row * FF + col) = make_float2(v0, v1);
            *(float2*)(g_buf + (size_t)(row + 8) * FF + col) = make_float2(v2, v3);
        }
    }
}

// ---------------- radix: key of the k-th largest value -------------------------
__device__ unsigned radix_thresh(const float* sA, int* hist, int* misc) {
    const int tid = threadIdx.x;  // 512 threads
    if (tid == 0) { misc[0] = 0; misc[1] = TK; }
    __syncthreads();
#pragma unroll
    for (int pass = 0; pass < 4; pass++) {
        int shift = 24 - 8 * pass;
        unsigned pm = (pass == 0) ? 0u : (0xFFFFFFFFu << (shift + 8));
        for (int i = tid; i < 256; i += 512) hist[i] = 0;
        __syncthreads();
        unsigned prefix = (unsigned)misc[0];
        for (int i = tid; i < FF; i += 512) {
            unsigned u = f2k(sA[i]);
            if ((u & pm) == prefix) atomicAdd(&hist[(u >> shift) & 255], 1);
        }
        __syncthreads();
        if (tid == 0) {
            int krem = misc[1], cum = 0, t = 0;
            for (int b = 255; b >= 0; b--) {
                int h = hist[b];
                if (cum + h >= krem) { t = b; break; }
                cum += h;
            }
            misc[0] = (int)(((unsigned)misc[0]) | ((unsigned)t << shift));
            misc[1] = krem - cum;
        }
        __syncthreads();
    }
    return (unsigned)misc[0];
}

// exact rank-select among <=CAP candidates; ties -> smallest index (lax.top_k)
__device__ void rank_select(const int* cidx, const float* cval, int nc,
                            float* oval, int* oidx) {
    for (int c = threadIdx.x; c < nc; c += 512) {
        float v = cval[c];
        int j = cidx[c];
        int rank = 0;
        for (int t = 0; t < nc; t++) {
            float vt = cval[t];
            rank += (vt > v) || (vt == v && cidx[t] < j);
        }
        if (rank < TK) { oidx[rank] = j; oval[rank] = v; }
    }
}

// ---------------- upstream: approx threshold -> exact fp32 refinement ---------
__global__ void k_topk_up_ref(const float* __restrict__ x, const float* __restrict__ W) {
    extern __shared__ unsigned smu[];
    float* sA = (float*)smu;           // FF floats
    int* hist = (int*)(smu + FF);
    int* misc = hist + 256;            // 8 ints
    int* cidx = misc + 8;              // CAP
    float* cval = (float*)(cidx + CAP);
    int row = blockIdx.x;
    const int tid = threadIdx.x;
    const float* src = g_buf + (size_t)row * FF;
    for (int i = tid; i < FF; i += 512) sA[i] = src[i];
    __syncthreads();
    unsigned T = radix_thresh(sA, hist, misc);
    float cutoff = k2f(T) - MARGIN;
    if (tid == 0) misc[4] = 0;
    __syncthreads();
    for (int i = tid; i < FF; i += 512)
        if (sA[i] >= cutoff) {
            int p = atomicAdd(&misc[4], 1);
            if (p < CAP) cidx[p] = i;
        }
    __syncthreads();
    int nc = min(misc[4], CAP);
    // cache x row in shared (reuse sA front)
    const float* xr = x + (size_t)row * DD;
    float* sx = sA;
    for (int i = tid; i < DD; i += 512) sx[i] = xr[i];
    __syncthreads();
    int warp = tid >> 5, lane = tid & 31;
    for (int c = warp; c < nc; c += 16) {
        const float* wr = W + (size_t)cidx[c] * DD;
        float s = 0.f;
#pragma unroll
        for (int t = 0; t < 6; t++) {
            int off = lane * 4 + t * 128;
            float4 a = *(const float4*)(wr + off);
            float4 b = *(const float4*)(sx + off);
            s += a.x * b.x + a.y * b.y + a.z * b.z + a.w * b.w;
        }
        s = warp_red(s);
        if (lane == 0) cval[c] = fmaxf(s + g_add1[cidx[c]], 0.f);
    }
    __syncthreads();
    rank_select(cidx, cval, nc, g_upval + row * TK, g_upidx + row * TK);
}

// ---------------- downstream: contribs scatter + refine + select ---------------
__global__ void k_contrib_topk_ref(const float* __restrict__ x, const float* __restrict__ W) {
    extern __shared__ unsigned smu[];
    float* sA = (float*)smu;
    int* hist = (int*)(smu + FF);
    int* misc = hist + 256;
    int* cidx = misc + 8;
    float* cval = (float*)(cidx + CAP);
    float* cextra = cval + CAP;
    __shared__ int sj[TK];
    __shared__ float sv[TK];
    int row = blockIdx.x;
    const int tid = threadIdx.x;
    const float* src = g_buf + (size_t)row * FF;
    for (int i = tid; i < FF; i += 512) sA[i] = src[i];
    if (tid < TK) {
        sj[tid] = g_upidx[row * TK + tid];
        sv[tid] = g_upval[row * TK + tid];
    }
    __syncthreads();
    for (int s = 0; s < TK; s++) {
        int j = sj[s];
        float v = sv[s];
        int e0 = g_colptr[j];
        int e1 = g_colptr[j + 1];
        if (e1 > NNZ_MAX) e1 = NNZ_MAX;
        for (int e = e0 + tid; e < e1; e += 512)
            sA[g_rowidx[e]] += v * g_mval[e];  // distinct fd within a column
        __syncthreads();
    }
    unsigned T = radix_thresh(sA, hist, misc);
    float cutoff = k2f(T) - MARGIN;
    if (tid == 0) misc[4] = 0;
    __syncthreads();
    for (int i = tid; i < FF; i += 512)
        if (sA[i] >= cutoff) {
            int p = atomicAdd(&misc[4], 1);
            if (p < CAP) cidx[p] = i;
        }
    __syncthreads();
    int nc = min(misc[4], CAP);
    // contribs_j (exact fp32) = scattered - approx_base
    for (int c = tid; c < nc; c += 512)
        cextra[c] = sA[cidx[c]] - src[cidx[c]];
    __syncthreads();
    const float* xr = x + (size_t)row * DD;
    float* sx = sA;
    for (int i = tid; i < DD; i += 512) sx[i] = xr[i];
    __syncthreads();
    int warp = tid >> 5, lane = tid & 31;
    for (int c = warp; c < nc; c += 16) {
        const float* wr = W + (size_t)cidx[c] * DD;
        float s = 0.f;
#pragma unroll
        for (int t = 0; t < 6; t++) {
            int off = lane * 4 + t * 128;
            float4 a = *(const float4*)(wr + off);
            float4 b = *(const float4*)(sx + off);
            s += a.x * b.x + a.y * b.y + a.z * b.z + a.w * b.w;
        }
        s = warp_red(s);
        if (lane == 0) cval[c] = s + g_add2[cidx[c]] + cextra[c];
    }
    __syncthreads();
    rank_select(cidx, cval, nc, g_dnval + row * TK, g_dnidx + row * TK);
}

// ---------------- decode -------------------------------------------------------
__global__ void k_decode(const float* __restrict__ bdd, float* __restrict__ out) {
    __shared__ float vj[TK];
    __shared__ int ij[TK];
    int row = blockIdx.x;
    if (threadIdx.x < TK) {
        vj[threadIdx.x] = g_dnval[row * TK + threadIdx.x];
        ij[threadIdx.x] = g_dnidx[row * TK + threadIdx.x];
    }
    __syncthreads();
    int d = threadIdx.x;  // blockDim == 768
    float acc = bdd[d];
#pragma unroll 8
    for (int s = 0; s < TK; s++)
        acc += vj[s] * g_WdecDnT[(size_t)ij[s] * DD + d];
    out[(size_t)row * DD + d] = acc;
}

// ---------------- launch --------------------------------------------------------
extern "C" void kernel_launch(void* const* d_in, const int* in_sizes, int n_in,
                              void* d_out, int out_size) {
    const float* x_up      = (const float*)d_in[0];
    const float* x_resid   = (const float*)d_in[1];
    const float* W_enc_up  = (const float*)d_in[2];
    const float* b_enc_up  = (const float*)d_in[3];
    const float* b_dec_up  = (const float*)d_in[4];
    const float* W_dec_up  = (const float*)d_in[5];
    const float* W_enc_down= (const float*)d_in[6];
    const float* b_enc_down= (const float*)d_in[7];
    const float* b_dec_down= (const float*)d_in[8];
    const float* W_dec_down= (const float*)d_in[9];
    const void*  conn_mask = d_in[10];
    float* out = (float*)d_out;

    __nv_bfloat16 *a1h, *a2h, *b1h, *b2h;
    cudaGetSymbolAddress((void**)&a1h, g_A1h);
    cudaGetSymbolAddress((void**)&a2h, g_A2h);
    cudaGetSymbolAddress((void**)&b1h, g_B1h);
    cudaGetSymbolAddress((void**)&b2h, g_B2h);

    cudaFuncSetAttribute(k_topk_up_ref, cudaFuncAttributeMaxDynamicSharedMemorySize, SMEM_REF);
    cudaFuncSetAttribute(k_contrib_topk_ref, cudaFuncAttributeMaxDynamicSharedMemorySize, SMEM_REF);
    cudaFuncSetAttribute(k_gemm_mma, cudaFuncAttributeMaxDynamicSharedMemorySize, GM_SMEM);

    k_init<<<48, 256>>>();
    k_detect<<<1024, 256>>>((const unsigned*)conn_mask);
    k_cvt<<<MR * DD / 4 / 256, 256>>>(x_up, a1h);
    k_cvt<<<MR * DD / 4 / 256, 256>>>(x_resid, a2h);
    k_cvt<<<FF * DD / 4 / 256, 256>>>(W_enc_up, b1h);
    k_cvt<<<FF * DD / 4 / 256, 256>>>(W_enc_down, b2h);
    k_transpose<<<dim3(384, 24), dim3(32, 8)>>>(W_dec_up, 0);
    k_transpose<<<dim3(384, 24), dim3(32, 8)>>>(W_dec_down, 1);
    k_addvec<<<1536, 256>>>(W_enc_up, b_enc_up, b_dec_up, W_enc_down, b_enc_down);
    k_maskcount<<<FF, 256>>>(conn_mask);
    k_scan<<<1, 1024>>>();
    k_maskfill<<<FF, 256>>>(conn_mask);
    k_mval<<<FF, 256>>>(W_enc_down);
    k_gemm_mma<<<dim3(96, 32), 256, GM_SMEM>>>(a1h, b1h, 0, 1);
    k_topk_up_ref<<<MR, 512, SMEM_REF>>>(x_up, W_enc_up);
    k_gemm_mma<<<dim3(96, 32), 256, GM_SMEM>>>(a2h, b2h, 1, 0);
    k_contrib_topk_ref<<<MR, 512, SMEM_REF>>>(x_resid, W_enc_down);
    k_decode<<<MR, 768>>>(b_dec_down, out);
}

// round 7
// speedup vs baseline: 1.9193x; 1.1596x over previous
#include <cuda_runtime.h>
#include <cuda_bf16.h>
#include <stdint.h>

#define MR   4096      // B*S rows
#define DD   768       // D
#define FF   12288     // F
#define TK   64        // top-k
#define NNZ_MAX (1 << 22)
#define CAP 384
#define MARGIN 0.08f
#define FXSCALE 4194304.0f          // 2^22
#define FXINV   (1.0f / 4194304.0f)
#define SMEM_REF1 (FF*4 + 256*4 + 32 + CAP*8)
#define SMEM_REF2 (FF*8 + 256*4 + 32 + CAP*12)

// GEMM tiling (pure bf16; exact refinement makes noise harmless)
#define KC 32
#define NCHUNK (DD / KC)          // 24
#define STAGES 3
#define LDSS 40                   // smem row stride in bf16 (80B, ldmatrix conflict-free)
#define TILE_B (128 * LDSS * 2)   // 10240 bytes per tile
#define STAGE_B (2 * TILE_B)      // A|B
#define GM_SMEM (STAGES * STAGE_B)

// ---------------- device scratch (static; no runtime allocation) -------------
__device__ __nv_bfloat16 g_buf1[(size_t)MR * FF];   // up_pre approx (bf16)
__device__ __nv_bfloat16 g_buf2[(size_t)MR * FF];   // initial approx (bf16)
__device__ float g_WdecUpT[(size_t)FF * DD];
__device__ float g_WdecDnT[(size_t)FF * DD];
__device__ float g_add1[FF];
__device__ float g_add2[FF];
__device__ int   g_colcnt[FF];
__device__ int   g_colfill[FF];
__device__ int   g_colptr[FF + 1];
__device__ int   g_rowidx[NNZ_MAX];
__device__ float g_mval[NNZ_MAX];
__device__ float g_upval[MR * TK];
__device__ int   g_upidx[MR * TK];
__device__ float g_dnval[MR * TK];
__device__ int   g_dnidx[MR * TK];
__device__ int   g_isb;
__device__ __nv_bfloat16 g_A1h[(size_t)MR * DD];
__device__ __nv_bfloat16 g_A2h[(size_t)MR * DD];
__device__ __nv_bfloat16 g_B1h[(size_t)FF * DD];
__device__ __nv_bfloat16 g_B2h[(size_t)FF * DD];

// ---------------- small helpers ----------------------------------------------
__device__ __forceinline__ unsigned f2k(float f) {
    unsigned u = __float_as_uint(f);
    return (u & 0x80000000u) ? ~u : (u | 0x80000000u);
}
__device__ __forceinline__ float k2f(unsigned u) {
    return __uint_as_float((u & 0x80000000u) ? (u ^ 0x80000000u) : ~u);
}
__device__ __forceinline__ uint32_t smem_u32(const void* p) {
    uint32_t a;
    asm("{ .reg .u64 t; cvta.to.shared.u64 t, %1; cvt.u32.u64 %0, t; }" : "=r"(a) : "l"(p));
    return a;
}
__device__ __forceinline__ uint32_t bf2u(__nv_bfloat162 h) {
    return *reinterpret_cast<uint32_t*>(&h);
}
__device__ __forceinline__ void cp16(uint32_t dst, const void* src) {
    asm volatile("cp.async.cg.shared.global [%0], [%1], 16;" :: "r"(dst), "l"(src));
}
__device__ __forceinline__ void ldm4(uint32_t* r, uint32_t a) {
    asm volatile("ldmatrix.sync.aligned.m8n8.x4.shared.b16 {%0,%1,%2,%3}, [%4];"
                 : "=r"(r[0]), "=r"(r[1]), "=r"(r[2]), "=r"(r[3]) : "r"(a));
}
__device__ __forceinline__ void mma_bf16(float* c, const uint32_t* a, const uint32_t* b) {
    asm volatile(
        "mma.sync.aligned.m16n8k16.row.col.f32.bf16.bf16.f32 "
        "{%0,%1,%2,%3}, {%4,%5,%6,%7}, {%8,%9}, {%0,%1,%2,%3};"
        : "+f"(c[0]), "+f"(c[1]), "+f"(c[2]), "+f"(c[3])
        : "r"(a[0]), "r"(a[1]), "r"(a[2]), "r"(a[3]), "r"(b[0]), "r"(b[1]));
}
__device__ __forceinline__ float warp_red(float s) {
#pragma unroll
    for (int o = 16; o; o >>= 1) s += __shfl_xor_sync(0xFFFFFFFFu, s, o);
    return s;
}

// ---------------- init + mask format detection -------------------------------
__global__ void k_init() {
    int i = blockIdx.x * blockDim.x + threadIdx.x;
    if (i < FF) { g_colcnt[i] = 0; g_colfill[i] = 0; }
    if (i == 0) g_isb = 0;
}

__global__ void k_detect(const unsigned* __restrict__ m) {
    unsigned gid = blockIdx.x * blockDim.x + threadIdx.x;
    bool isb = false;
#pragma unroll
    for (int t = 0; t < 16; t++) {
        unsigned v = m[gid + (unsigned)t * 262144u];
        bool bytes01 = ((v & 0xFEFEFEFEu) == 0u);
        isb |= (v > 1u) && bytes01;
    }
    if (__ballot_sync(0xFFFFFFFFu, isb) && (threadIdx.x & 31) == 0)
        atomicOr(&g_isb, 1);
}

// ---------------- fp32 -> bf16 conversion (all 4 operands, one launch) --------
__global__ void k_cvt_all(const float* __restrict__ xu, const float* __restrict__ xr,
                          const float* __restrict__ weu, const float* __restrict__ wed,
                          __nv_bfloat16* __restrict__ a1, __nv_bfloat16* __restrict__ a2,
                          __nv_bfloat16* __restrict__ b1, __nv_bfloat16* __restrict__ b2) {
    const int N1 = MR * DD / 4, N2 = FF * DD / 4;
    int i = blockIdx.x * blockDim.x + threadIdx.x;
    const float* src; __nv_bfloat16* dst; int idx;
    if (i < N1)                { src = xu;  dst = a1; idx = i; }
    else if (i < 2 * N1)       { src = xr;  dst = a2; idx = i - N1; }
    else if (i < 2 * N1 + N2)  { src = weu; dst = b1; idx = i - 2 * N1; }
    else                       { src = wed; dst = b2; idx = i - 2 * N1 - N2; }
    float4 v = ((const float4*)src)[idx];
    __nv_bfloat162 h0 = __floats2bfloat162_rn(v.x, v.y);
    __nv_bfloat162 h1 = __floats2bfloat162_rn(v.z, v.w);
    ((uint2*)dst)[idx] = make_uint2(bf2u(h0), bf2u(h1));
}

// ---------------- transpose [DD, FF] -> [FF, DD] ------------------------------
__global__ void k_transpose(const float* __restrict__ in, int which) {
    __shared__ float t[32][33];
    float* out = which ? g_WdecDnT : g_WdecUpT;
    int bf = blockIdx.x * 32, bd = blockIdx.y * 32;
    int x = threadIdx.x, y = threadIdx.y;
#pragma unroll
    for (int r = 0; r < 32; r += 8)
        t[y + r][x] = in[(size_t)(bd + y + r) * FF + bf + x];
    __syncthreads();
#pragma unroll
    for (int r = 0; r < 32; r += 8)
        out[(size_t)(bf + y + r) * DD + bd + x] = t[x][y + r];
}

// ---------------- bias vectors ------------------------------------------------
__global__ void k_addvec(const float* __restrict__ Weu, const float* __restrict__ beu,
                         const float* __restrict__ bdu, const float* __restrict__ Wed,
                         const float* __restrict__ bed) {
    int warp = threadIdx.x >> 5, lane = threadIdx.x & 31;
    int n = blockIdx.x * 8 + warp;
    const float* r1 = Weu + (size_t)n * DD;
    const float* r2 = Wed + (size_t)n * DD;
    float s1 = 0.f, s2 = 0.f;
#pragma unroll
    for (int t = 0; t < 6; t++) {
        int off = lane * 4 + t * 128;
        float4 bv = *(const float4*)(bdu + off);
        float4 w1 = *(const float4*)(r1 + off);
        float4 w2 = *(const float4*)(r2 + off);
        s1 += bv.x * w1.x + bv.y * w1.y + bv.z * w1.z + bv.w * w1.w;
        s2 += bv.x * w2.x + bv.y * w2.y + bv.z * w2.z + bv.w * w2.w;
    }
    s1 = warp_red(s1); s2 = warp_red(s2);
    if (lane == 0) {
        g_add1[n] = beu[n] - s1;
        g_add2[n] = bed[n] + s2;
    }
}

// ---------------- CSC build of masked virtual matrix -------------------------
__global__ void k_maskcount(const void* __restrict__ maskp) {
    int fd = blockIdx.x;
    if (g_isb) {
        const unsigned* row = (const unsigned*)maskp + (size_t)fd * (FF / 4);
        for (int w = threadIdx.x; w < FF / 4; w += blockDim.x) {
            unsigned v = row[w];
            if (v) {
#pragma unroll
                for (int b = 0; b < 4; b++)
                    if ((v >> (8 * b)) & 0xFFu) atomicAdd(&g_colcnt[w * 4 + b], 1);
            }
        }
    } else {
        const unsigned* row = (const unsigned*)maskp + (size_t)fd * FF;
        for (int j = threadIdx.x; j < FF; j += blockDim.x)
            if (row[j]) atomicAdd(&g_colcnt[j], 1);
    }
}

__global__ void k_scan() {
    __shared__ int partial[1024];
    int tid = threadIdx.x;
    int base = tid * 12;
    int loc[12];
    int s = 0;
#pragma unroll
    for (int t = 0; t < 12; t++) { loc[t] = s; s += g_colcnt[base + t]; }
    partial[tid] = s;
    __syncthreads();
    for (int off = 1; off < 1024; off <<= 1) {
        int v = (tid >= off) ? partial[tid - off] : 0;
        __syncthreads();
        partial[tid] += v;
        __syncthreads();
    }
    int excl = (tid == 0) ? 0 : partial[tid - 1];
#pragma unroll
    for (int t = 0; t < 12; t++) g_colptr[base + t] = excl + loc[t];
    if (tid == 1023) g_colptr[FF] = partial[1023];
}

__global__ void k_maskfill(const void* __restrict__ maskp) {
    int fd = blockIdx.x;
    if (g_isb) {
        const unsigned* row = (const unsigned*)maskp + (size_t)fd * (FF / 4);
        for (int w = threadIdx.x; w < FF / 4; w += blockDim.x) {
            unsigned v = row[w];
            if (v) {
#pragma unroll
                for (int b = 0; b < 4; b++)
                    if ((v >> (8 * b)) & 0xFFu) {
                        int j = w * 4 + b;
                        int pos = g_colptr[j] + atomicAdd(&g_colfill[j], 1);
                        if (pos < NNZ_MAX) g_rowidx[pos] = fd;
                    }
            }
        }
    } else {
        const unsigned* row = (const unsigned*)maskp + (size_t)fd * FF;
        for (int j = threadIdx.x; j < FF; j += blockDim.x)
            if (row[j]) {
                int pos = g_colptr[j] + atomicAdd(&g_colfill[j], 1);
                if (pos < NNZ_MAX) g_rowidx[pos] = fd;
            }
    }
}

// SDDMM for mask nonzeros
__global__ void k_mval(const float* __restrict__ Wed) {
    __shared__ float swd[DD];
    int j = blockIdx.x;
    const float* wdrow = g_WdecUpT + (size_t)j * DD;
    for (int i = threadIdx.x; i < DD; i += blockDim.x) swd[i] = wdrow[i];
    __syncthreads();
    int e0 = g_colptr[j];
    int e1 = g_colptr[j + 1];
    if (e1 > NNZ_MAX) e1 = NNZ_MAX;
    int warp = threadIdx.x >> 5, lane = threadIdx.x & 31;
    for (int e = e0 + warp; e < e1; e += (int)blockDim.x / 32) {
        int fd = g_rowidx[e];
        const float* wr = Wed + (size_t)fd * DD;
        float s = 0.f;
#pragma unroll
        for (int t = 0; t < 6; t++) {
            int off = lane * 4 + t * 128;
            float4 a = *(const float4*)(wr + off);
            float4 b = *(const float4*)(swd + off);
            s += a.x * b.x + a.y * b.y + a.z * b.z + a.w * b.w;
        }
        s = warp_red(s);
        if (lane == 0) g_mval[e] = s;
    }
}

// ---------------- bf16 HMMA GEMM (NT), both stages in one launch --------------
__global__ void __launch_bounds__(256, 2)
k_gemm_mma(const __nv_bfloat16* __restrict__ A1, const __nv_bfloat16* __restrict__ B1,
           const __nv_bfloat16* __restrict__ A2, const __nv_bfloat16* __restrict__ B2) {
    extern __shared__ char smraw[];
    const uint32_t sbase = smem_u32(smraw);
    const int z = blockIdx.z;
    const __nv_bfloat16* Ah = z ? A2 : A1;
    const __nv_bfloat16* Bh = z ? B2 : B1;
    __nv_bfloat16* outp = z ? g_buf2 : g_buf1;
    const float* addv = z ? g_add2 : g_add1;
    const int do_relu = (z == 0);
    const int tid = threadIdx.x;
    const int wid = tid >> 5, lane = tid & 31;
    const int bm = blockIdx.y * 128, bn = blockIdx.x * 128;
    const int wm = (wid & 1) * 64, wn = (wid >> 1) * 32;

    const int rr = tid >> 2, q = tid & 3;
    const __nv_bfloat16* srcA = Ah + (size_t)(bm + rr) * DD + q * 8;
    const __nv_bfloat16* srcB = Bh + (size_t)(bn + rr) * DD + q * 8;
    const uint32_t dst0 = sbase + rr * (LDSS * 2) + q * 16;

    float acc[4][4][4];
#pragma unroll
    for (int i = 0; i < 4; i++)
#pragma unroll
        for (int j = 0; j < 4; j++)
#pragma unroll
            for (int k = 0; k < 4; k++) acc[i][j][k] = 0.f;

#pragma unroll
    for (int s = 0; s < STAGES; s++) {
        int k0 = s * KC;
        uint32_t db = dst0 + s * STAGE_B;
        cp16(db, srcA + k0);
        cp16(db + 64 * (LDSS * 2), srcA + k0 + (size_t)64 * DD);
        cp16(db + TILE_B, srcB + k0);
        cp16(db + TILE_B + 64 * (LDSS * 2), srcB + k0 + (size_t)64 * DD);
        asm volatile("cp.async.commit_group;" ::: "memory");
    }

#pragma unroll 1
    for (int c = 0; c < NCHUNK; c++) {
        asm volatile("cp.async.wait_group %0;" :: "n"(STAGES - 1) : "memory");
        __syncthreads();
        int st = c % STAGES;
        uint32_t sA = sbase + st * STAGE_B;
        uint32_t sB = sA + TILE_B;
#pragma unroll
        for (int kk = 0; kk < KC / 16; kk++) {
            uint32_t ah[4][4], bh[4][2];
            int arow = wm + (lane & 15);
            int acol = kk * 16 + (lane >> 4) * 8;
#pragma unroll
            for (int f = 0; f < 4; f++)
                ldm4(ah[f], sA + (uint32_t)((arow + f * 16) * LDSS + acol) * 2);
            int brow = wn + ((lane >> 4) << 3) + (lane & 7);
            int bcol = kk * 16 + ((lane >> 3) & 1) * 8;
#pragma unroll
            for (int g = 0; g < 2; g++) {
                uint32_t r4[4];
                ldm4(r4, sB + (uint32_t)((brow + g * 16) * LDSS + bcol) * 2);
                bh[g * 2][0] = r4[0]; bh[g * 2][1] = r4[1];
                bh[g * 2 + 1][0] = r4[2]; bh[g * 2 + 1][1] = r4[3];
            }
#pragma unroll
            for (int mi = 0; mi < 4; mi++)
#pragma unroll
                for (int ni = 0; ni < 4; ni++)
                    mma_bf16(acc[mi][ni], ah[mi], bh[ni]);
        }
        __syncthreads();
        if (c + STAGES < NCHUNK) {
            int k0 = (c + STAGES) * KC;
            uint32_t db = dst0 + st * STAGE_B;
            cp16(db, srcA + k0);
            cp16(db + 64 * (LDSS * 2), srcA + k0 + (size_t)64 * DD);
            cp16(db + TILE_B, srcB + k0);
            cp16(db + TILE_B + 64 * (LDSS * 2), srcB + k0 + (size_t)64 * DD);
        }
        asm volatile("cp.async.commit_group;" ::: "memory");
    }

#pragma unroll
    for (int ni = 0; ni < 4; ni++) {
        int col = bn + wn + ni * 8 + (lane & 3) * 2;
        float a0 = addv[col], a1 = addv[col + 1];
#pragma unroll
        for (int mi = 0; mi < 4; mi++) {
            int row = bm + wm + mi * 16 + (lane >> 2);
            float v0 = acc[mi][ni][0] + a0;
            float v1 = acc[mi][ni][1] + a1;
            float v2 = acc[mi][ni][2] + a0;
            float v3 = acc[mi][ni][3] + a1;
            if (do_relu) {
                v0 = fmaxf(v0, 0.f); v1 = fmaxf(v1, 0.f);
                v2 = fmaxf(v2, 0.f); v3 = fmaxf(v3, 0.f);
            }
            *(uint32_t*)(outp + (size_t)row * FF + col) =
                bf2u(__floats2bfloat162_rn(v0, v1));
            *(uint32_t*)(outp + (size_t)(row + 8) * FF + col) =
                bf2u(__floats2bfloat162_rn(v2, v3));
        }
    }
}

// ---------------- radix: key of the k-th largest value -------------------------
__device__ unsigned radix_thresh(const float* sA, int* hist, int* misc) {
    const int tid = threadIdx.x;  // 512 threads
    if (tid == 0) { misc[0] = 0; misc[1] = TK; }
    __syncthreads();
#pragma unroll
    for (int pass = 0; pass < 4; pass++) {
        int shift = 24 - 8 * pass;
        unsigned pm = (pass == 0) ? 0u : (0xFFFFFFFFu << (shift + 8));
        for (int i = tid; i < 256; i += 512) hist[i] = 0;
        __syncthreads();
        unsigned prefix = (unsigned)misc[0];
        for (int i = tid; i < FF; i += 512) {
            unsigned u = f2k(sA[i]);
            if ((u & pm) == prefix) atomicAdd(&hist[(u >> shift) & 255], 1);
        }
        __syncthreads();
        if (tid == 0) {
            int krem = misc[1], cum = 0, t = 0;
            for (int b = 255; b >= 0; b--) {
                int h = hist[b];
                if (cum + h >= krem) { t = b; break; }
                cum += h;
            }
            misc[0] = (int)(((unsigned)misc[0]) | ((unsigned)t << shift));
            misc[1] = krem - cum;
        }
        __syncthreads();
    }
    return (unsigned)misc[0];
}

// exact rank-select among <=CAP candidates; ties -> smallest index (lax.top_k)
__device__ void rank_select(const int* cidx, const float* cval, int nc,
                            float* oval, int* oidx) {
    for (int c = threadIdx.x; c < nc; c += 512) {
        float v = cval[c];
        int j = cidx[c];
        int rank = 0;
        for (int t = 0; t < nc; t++) {
            float vt = cval[t];
            rank += (vt > v) || (vt == v && cidx[t] < j);
        }
        if (rank < TK) { oidx[rank] = j; oval[rank] = v; }
    }
}

// ---------------- upstream: approx threshold -> exact fp32 refinement ---------
__global__ void k_topk_up_ref(const float* __restrict__ x, const float* __restrict__ W) {
    extern __shared__ unsigned smu[];
    float* sA = (float*)smu;           // FF floats
    int* hist = (int*)(smu + FF);
    int* misc = hist + 256;            // 8 ints
    int* cidx = misc + 8;              // CAP
    float* cval = (float*)(cidx + CAP);
    int row = blockIdx.x;
    const int tid = threadIdx.x;
    const __nv_bfloat16* src = g_buf1 + (size_t)row * FF;
    for (int i = tid; i < FF; i += 512) sA[i] = __bfloat162float(src[i]);
    __syncthreads();
    unsigned T = radix_thresh(sA, hist, misc);
    float cutoff = k2f(T) - MARGIN;
    if (tid == 0) misc[4] = 0;
    __syncthreads();
    for (int i = tid; i < FF; i += 512)
        if (sA[i] >= cutoff) {
            int p = atomicAdd(&misc[4], 1);
            if (p < CAP) cidx[p] = i;
        }
    __syncthreads();
    int nc = min(misc[4], CAP);
    const float* xr = x + (size_t)row * DD;
    float* sx = sA;
    for (int i = tid; i < DD; i += 512) sx[i] = xr[i];
    __syncthreads();
    int warp = tid >> 5, lane = tid & 31;
    for (int c = warp; c < nc; c += 16) {
        const float* wr = W + (size_t)cidx[c] * DD;
        float s = 0.f;
#pragma unroll
        for (int t = 0; t < 6; t++) {
            int off = lane * 4 + t * 128;
            float4 a = *(const float4*)(wr + off);
            float4 b = *(const float4*)(sx + off);
            s += a.x * b.x + a.y * b.y + a.z * b.z + a.w * b.w;
        }
        s = warp_red(s);
        if (lane == 0) cval[c] = fmaxf(s + g_add1[cidx[c]], 0.f);
    }
    __syncthreads();
    rank_select(cidx, cval, nc, g_upval + row * TK, g_upidx + row * TK);
}

// ---------------- downstream: parallel fx scatter + refine + select ------------
__global__ void k_contrib_topk_ref(const float* __restrict__ x, const float* __restrict__ W) {
    extern __shared__ unsigned smu[];
    float* sA = (float*)smu;            // FF floats
    int* fx = (int*)(smu + FF);         // FF ints (fixed-point contribs)
    int* hist = fx + FF;
    int* misc = hist + 256;
    int* cidx = misc + 8;
    float* cval = (float*)(cidx + CAP);
    float* cextra = cval + CAP;
    __shared__ int sj[TK];
    __shared__ float sv[TK];
    int row = blockIdx.x;
    const int tid = threadIdx.x;
    const int wid = tid >> 5, lane = tid & 31;
    const __nv_bfloat16* src = g_buf2 + (size_t)row * FF;
    for (int i = tid; i < FF; i += 512) fx[i] = 0;
    if (tid < TK) {
        sj[tid] = g_upidx[row * TK + tid];
        sv[tid] = g_upval[row * TK + tid];
    }
    __syncthreads();
    // parallel deterministic scatter: int fixed-point atomics (associative)
#pragma unroll
    for (int s4 = 0; s4 < 4; s4++) {
        int s = wid + s4 * 16;
        int j = sj[s];
        float v = sv[s];
        int e0 = g_colptr[j];
        int e1 = g_colptr[j + 1];
        if (e1 > NNZ_MAX) e1 = NNZ_MAX;
        for (int e = e0 + lane; e < e1; e += 32) {
            int q = __float2int_rn(v * g_mval[e] * FXSCALE);
            atomicAdd(&fx[g_rowidx[e]], q);
        }
    }
    __syncthreads();
    for (int i = tid; i < FF; i += 512)
        sA[i] = __bfloat162float(src[i]) + (float)fx[i] * FXINV;
    __syncthreads();
    unsigned T = radix_thresh(sA, hist, misc);
    float cutoff = k2f(T) - MARGIN;
    if (tid == 0) misc[4] = 0;
    __syncthreads();
    for (int i = tid; i < FF; i += 512)
        if (sA[i] >= cutoff) {
            int p = atomicAdd(&misc[4], 1);
            if (p < CAP) cidx[p] = i;
        }
    __syncthreads();
    int nc = min(misc[4], CAP);
    for (int c = tid; c < nc; c += 512)
        cextra[c] = (float)fx[cidx[c]] * FXINV;   // contribs (quantized 2^-22)
    __syncthreads();
    const float* xr = x + (size_t)row * DD;
    float* sx = sA;
    for (int i = tid; i < DD; i += 512) sx[i] = xr[i];
    __syncthreads();
    for (int c = wid; c < nc; c += 16) {
        const float* wr = W + (size_t)cidx[c] * DD;
        float s = 0.f;
#pragma unroll
        for (int t = 0; t < 6; t++) {
            int off = lane * 4 + t * 128;
            float4 a = *(const float4*)(wr + off);
            float4 b = *(const float4*)(sx + off);
            s += a.x * b.x + a.y * b.y + a.z * b.z + a.w * b.w;
        }
        s = warp_red(s);
        if (lane == 0) cval[c] = s + g_add2[cidx[c]] + cextra[c];
    }
    __syncthreads();
    rank_select(cidx, cval, nc, g_dnval + row * TK, g_dnidx + row * TK);
}

// ---------------- decode -------------------------------------------------------
__global__ void k_decode(const float* __restrict__ bdd, float* __restrict__ out) {
    __shared__ float vj[TK];
    __shared__ int ij[TK];
    int row = blockIdx.x;
    if (threadIdx.x < TK) {
        vj[threadIdx.x] = g_dnval[row * TK + threadIdx.x];
        ij[threadIdx.x] = g_dnidx[row * TK + threadIdx.x];
    }
    __syncthreads();
    int d = threadIdx.x;  // blockDim == 768
    float acc = bdd[d];
#pragma unroll 8
    for (int s = 0; s < TK; s++)
        acc += vj[s] * g_WdecDnT[(size_t)ij[s] * DD + d];
    out[(size_t)row * DD + d] = acc;
}

// ---------------- launch --------------------------------------------------------
extern "C" void kernel_launch(void* const* d_in, const int* in_sizes, int n_in,
                              void* d_out, int out_size) {
    const float* x_up      = (const float*)d_in[0];
    const float* x_resid   = (const float*)d_in[1];
    const float* W_enc_up  = (const float*)d_in[2];
    const float* b_enc_up  = (const float*)d_in[3];
    const float* b_dec_up  = (const float*)d_in[4];
    const float* W_dec_up  = (const float*)d_in[5];
    const float* W_enc_down= (const float*)d_in[6];
    const float* b_enc_down= (const float*)d_in[7];
    const float* b_dec_down= (const float*)d_in[8];
    const float* W_dec_down= (const float*)d_in[9];
    const void*  conn_mask = d_in[10];
    float* out = (float*)d_out;

    __nv_bfloat16 *a1h, *a2h, *b1h, *b2h;
    cudaGetSymbolAddress((void**)&a1h, g_A1h);
    cudaGetSymbolAddress((void**)&a2h, g_A2h);
    cudaGetSymbolAddress((void**)&b1h, g_B1h);
    cudaGetSymbolAddress((void**)&b2h, g_B2h);

    cudaFuncSetAttribute(k_topk_up_ref, cudaFuncAttributeMaxDynamicSharedMemorySize, SMEM_REF1);
    cudaFuncSetAttribute(k_contrib_topk_ref, cudaFuncAttributeMaxDynamicSharedMemorySize, SMEM_REF2);
    cudaFuncSetAttribute(k_gemm_mma, cudaFuncAttributeMaxDynamicSharedMemorySize, GM_SMEM);

    const int NCVT = (2 * MR * DD / 4 + 2 * FF * DD / 4) / 256;
    k_init<<<48, 256>>>();
    k_detect<<<1024, 256>>>((const unsigned*)conn_mask);
    k_cvt_all<<<NCVT, 256>>>(x_up, x_resid, W_enc_up, W_enc_down, a1h, a2h, b1h, b2h);
    k_transpose<<<dim3(384, 24), dim3(32, 8)>>>(W_dec_up, 0);
    k_transpose<<<dim3(384, 24), dim3(32, 8)>>>(W_dec_down, 1);
    k_addvec<<<1536, 256>>>(W_enc_up, b_enc_up, b_dec_up, W_enc_down, b_enc_down);
    k_maskcount<<<FF, 256>>>(conn_mask);
    k_scan<<<1, 1024>>>();
    k_maskfill<<<FF, 256>>>(conn_mask);
    k_mval<<<FF, 256>>>(W_enc_down);
    k_gemm_mma<<<dim3(96, 32, 2), 256, GM_SMEM>>>(a1h, b1h, a2h, b2h);
    k_topk_up_ref<<<MR, 512, SMEM_REF1>>>(x_up, W_enc_up);
    k_contrib_topk_ref<<<MR, 512, SMEM_REF2>>>(x_resid, W_enc_down);
    k_decode<<<MR, 768>>>(b_dec_down, out);
}

// round 9
// speedup vs baseline: 2.2997x; 1.1982x over previous
#include <cuda_runtime.h>
#include <cuda_bf16.h>
#include <stdint.h>

#define MR   4096      // B*S rows
#define DD   768       // D
#define FF   12288     // F
#define TK   64        // top-k
#define NNZ_MAX (1 << 22)
#define CAP 384
#define MARGIN 0.08f
#define FXSCALE 4194304.0f          // 2^22
#define FXINV   (1.0f / 4194304.0f)

// GEMM tiling
#define KC 32
#define NCHUNK (DD / KC)          // 24
#define STAGES 3
#define LDSS 40                   // smem row stride in bf16 (80B, ldmatrix conflict-free)
#define TILE_B (128 * LDSS * 2)
#define STAGE_B (2 * TILE_B)
#define GM_SMEM (STAGES * STAGE_B)

// ---------------- device scratch ----------------------------------------------
__device__ __nv_bfloat16 g_buf1[(size_t)MR * FF];
__device__ __nv_bfloat16 g_buf2[(size_t)MR * FF];
__device__ float g_WdecUpT[(size_t)FF * DD];
__device__ float g_WdecDnT[(size_t)FF * DD];
__device__ float g_add1[FF];
__device__ float g_add2[FF];
__device__ int   g_colcnt[FF];
__device__ int   g_colfill[FF];
__device__ int   g_colptr[FF + 1];
__device__ int   g_rowidx[NNZ_MAX];
__device__ float g_mval[NNZ_MAX];
__device__ float g_upval[MR * TK];
__device__ int   g_upidx[MR * TK];
__device__ float g_dnval[MR * TK];
__device__ int   g_dnidx[MR * TK];
__device__ int   g_isb;
__device__ __nv_bfloat16 g_A1h[(size_t)MR * DD];
__device__ __nv_bfloat16 g_A2h[(size_t)MR * DD];
__device__ __nv_bfloat16 g_B1h[(size_t)FF * DD];
__device__ __nv_bfloat16 g_B2h[(size_t)FF * DD];

// ---------------- helpers -------------------------------------------------------
__device__ __forceinline__ unsigned key16(unsigned b) {   // b = bf16 bits
    return (b & 0x8000u) ? ((~b) & 0xFFFFu) : (b | 0x8000u);
}
__device__ __forceinline__ float val16(unsigned key) {
    unsigned b = (key & 0x8000u) ? (key ^ 0x8000u) : ((~key) & 0xFFFFu);
    return __uint_as_float(b << 16);
}
__device__ __forceinline__ uint32_t smem_u32(const void* p) {
    uint32_t a;
    asm("{ .reg .u64 t; cvta.to.shared.u64 t, %1; cvt.u32.u64 %0, t; }" : "=r"(a) : "l"(p));
    return a;
}
__device__ __forceinline__ uint32_t bf2u(__nv_bfloat162 h) {
    return *reinterpret_cast<uint32_t*>(&h);
}
__device__ __forceinline__ void cp16(uint32_t dst, const void* src) {
    asm volatile("cp.async.cg.shared.global [%0], [%1], 16;" :: "r"(dst), "l"(src));
}
__device__ __forceinline__ void ldm4(uint32_t* r, uint32_t a) {
    asm volatile("ldmatrix.sync.aligned.m8n8.x4.shared.b16 {%0,%1,%2,%3}, [%4];"
                 : "=r"(r[0]), "=r"(r[1]), "=r"(r[2]), "=r"(r[3]) : "r"(a));
}
__device__ __forceinline__ void mma_bf16(float* c, const uint32_t* a, const uint32_t* b) {
    asm volatile(
        "mma.sync.aligned.m16n8k16.row.col.f32.bf16.bf16.f32 "
        "{%0,%1,%2,%3}, {%4,%5,%6,%7}, {%8,%9}, {%0,%1,%2,%3};"
        : "+f"(c[0]), "+f"(c[1]), "+f"(c[2]), "+f"(c[3])
        : "r"(a[0]), "r"(a[1]), "r"(a[2]), "r"(a[3]), "r"(b[0]), "r"(b[1]));
}
__device__ __forceinline__ float warp_red(float s) {
#pragma unroll
    for (int o = 16; o; o >>= 1) s += __shfl_xor_sync(0xFFFFFFFFu, s, o);
    return s;
}
// divergence-SAFE warp-aggregated histogram add: ballot first, then match
// within the active mask only (convergent execution among active lanes).
__device__ __forceinline__ void hist_add(int* hist, unsigned b, bool act) {
    unsigned amask = __ballot_sync(0xFFFFFFFFu, act);
    if (act) {
        unsigned peers = __match_any_sync(amask, b);
        int lane = threadIdx.x & 31;
        int leader = __ffs(peers) - 1;
        if (lane == leader) atomicAdd(&hist[b], __popc(peers));
    }
}
// 32-lane parallel bucket pick: misc[0]=bucket, misc[out_k]=remaining-in-bucket
__device__ __forceinline__ void pick_bucket(int* hist, int* misc, int in_k, int out_k) {
    if (threadIdx.x < 32) {
        int lane = threadIdx.x;
        int base = lane * 8;
        int loc[8], s = 0;
#pragma unroll
        for (int t = 0; t < 8; t++) { loc[t] = hist[base + t]; s += loc[t]; }
        int suf = s;
#pragma unroll
        for (int off = 16; off; off >>= 1) {
            int o = __shfl_down_sync(0xFFFFFFFFu, suf, off);
            if (lane + off < 32) suf += o;
        }
        int krem = misc[in_k];
        int cumAbove = suf - s;
        for (int t = 7; t >= 0; t--) {
            if (cumAbove < krem && cumAbove + loc[t] >= krem) {
                misc[0] = base + t;
                misc[out_k] = krem - cumAbove;
            }
            cumAbove += loc[t];
        }
    }
}

// ---------------- init + mask detect --------------------------------------------
__global__ void k_init() {
    int i = blockIdx.x * blockDim.x + threadIdx.x;
    if (i < FF) { g_colcnt[i] = 0; g_colfill[i] = 0; }
    if (i == 0) g_isb = 0;
}
__global__ void k_detect(const unsigned* __restrict__ m) {
    unsigned gid = blockIdx.x * blockDim.x + threadIdx.x;
    bool isb = false;
#pragma unroll
    for (int t = 0; t < 16; t++) {
        unsigned v = m[gid + (unsigned)t * 262144u];
        bool bytes01 = ((v & 0xFEFEFEFEu) == 0u);
        isb |= (v > 1u) && bytes01;
    }
    if (__ballot_sync(0xFFFFFFFFu, isb) && (threadIdx.x & 31) == 0)
        atomicOr(&g_isb, 1);
}

// ---------------- fp32 -> bf16 (all 4 operands, one launch) ---------------------
__global__ void k_cvt_all(const float* __restrict__ xu, const float* __restrict__ xr,
                          const float* __restrict__ weu, const float* __restrict__ wed,
                          __nv_bfloat16* __restrict__ a1, __nv_bfloat16* __restrict__ a2,
                          __nv_bfloat16* __restrict__ b1, __nv_bfloat16* __restrict__ b2) {
    const int N1 = MR * DD / 4, N2 = FF * DD / 4;
    int i = blockIdx.x * blockDim.x + threadIdx.x;
    const float* src; __nv_bfloat16* dst; int idx;
    if (i < N1)                { src = xu;  dst = a1; idx = i; }
    else if (i < 2 * N1)       { src = xr;  dst = a2; idx = i - N1; }
    else if (i < 2 * N1 + N2)  { src = weu; dst = b1; idx = i - 2 * N1; }
    else                       { src = wed; dst = b2; idx = i - 2 * N1 - N2; }
    float4 v = ((const float4*)src)[idx];
    __nv_bfloat162 h0 = __floats2bfloat162_rn(v.x, v.y);
    __nv_bfloat162 h1 = __floats2bfloat162_rn(v.z, v.w);
    ((uint2*)dst)[idx] = make_uint2(bf2u(h0), bf2u(h1));
}

// ---------------- transpose -----------------------------------------------------
__global__ void k_transpose(const float* __restrict__ in, int which) {
    __shared__ float t[32][33];
    float* out = which ? g_WdecDnT : g_WdecUpT;
    int bf = blockIdx.x * 32, bd = blockIdx.y * 32;
    int x = threadIdx.x, y = threadIdx.y;
#pragma unroll
    for (int r = 0; r < 32; r += 8)
        t[y + r][x] = in[(size_t)(bd + y + r) * FF + bf + x];
    __syncthreads();
#pragma unroll
    for (int r = 0; r < 32; r += 8)
        out[(size_t)(bf + y + r) * DD + bd + x] = t[x][y + r];
}

// ---------------- bias vectors --------------------------------------------------
__global__ void k_addvec(const float* __restrict__ Weu, const float* __restrict__ beu,
                         const float* __restrict__ bdu, const float* __restrict__ Wed,
                         const float* __restrict__ bed) {
    int warp = threadIdx.x >> 5, lane = threadIdx.x & 31;
    int n = blockIdx.x * 8 + warp;
    const float* r1 = Weu + (size_t)n * DD;
    const float* r2 = Wed + (size_t)n * DD;
    float s1 = 0.f, s2 = 0.f;
#pragma unroll
    for (int t = 0; t < 6; t++) {
        int off = lane * 4 + t * 128;
        float4 bv = *(const float4*)(bdu + off);
        float4 w1 = *(const float4*)(r1 + off);
        float4 w2 = *(const float4*)(r2 + off);
        s1 += bv.x * w1.x + bv.y * w1.y + bv.z * w1.z + bv.w * w1.w;
        s2 += bv.x * w2.x + bv.y * w2.y + bv.z * w2.z + bv.w * w2.w;
    }
    s1 = warp_red(s1); s2 = warp_red(s2);
    if (lane == 0) {
        g_add1[n] = beu[n] - s1;
        g_add2[n] = bed[n] + s2;
    }
}

// ---------------- CSC build -----------------------------------------------------
__global__ void k_maskcount(const void* __restrict__ maskp) {
    int fd = blockIdx.x;
    if (g_isb) {
        const unsigned* row = (const unsigned*)maskp + (size_t)fd * (FF / 4);
        for (int w = threadIdx.x; w < FF / 4; w += blockDim.x) {
            unsigned v = row[w];
            if (v) {
#pragma unroll
                for (int b = 0; b < 4; b++)
                    if ((v >> (8 * b)) & 0xFFu) atomicAdd(&g_colcnt[w * 4 + b], 1);
            }
        }
    } else {
        const unsigned* row = (const unsigned*)maskp + (size_t)fd * FF;
        for (int j = threadIdx.x; j < FF; j += blockDim.x)
            if (row[j]) atomicAdd(&g_colcnt[j], 1);
    }
}
__global__ void k_scan() {
    __shared__ int partial[1024];
    int tid = threadIdx.x;
    int base = tid * 12;
    int loc[12];
    int s = 0;
#pragma unroll
    for (int t = 0; t < 12; t++) { loc[t] = s; s += g_colcnt[base + t]; }
    partial[tid] = s;
    __syncthreads();
    for (int off = 1; off < 1024; off <<= 1) {
        int v = (tid >= off) ? partial[tid - off] : 0;
        __syncthreads();
        partial[tid] += v;
        __syncthreads();
    }
    int excl = (tid == 0) ? 0 : partial[tid - 1];
#pragma unroll
    for (int t = 0; t < 12; t++) g_colptr[base + t] = excl + loc[t];
    if (tid == 1023) g_colptr[FF] = partial[1023];
}
__global__ void k_maskfill(const void* __restrict__ maskp) {
    int fd = blockIdx.x;
    if (g_isb) {
        const unsigned* row = (const unsigned*)maskp + (size_t)fd * (FF / 4);
        for (int w = threadIdx.x; w < FF / 4; w += blockDim.x) {
            unsigned v = row[w];
            if (v) {
#pragma unroll
                for (int b = 0; b < 4; b++)
                    if ((v >> (8 * b)) & 0xFFu) {
                        int j = w * 4 + b;
                        int pos = g_colptr[j] + atomicAdd(&g_colfill[j], 1);
                        if (pos < NNZ_MAX) g_rowidx[pos] = fd;
                    }
            }
        }
    } else {
        const unsigned* row = (const unsigned*)maskp + (size_t)fd * FF;
        for (int j = threadIdx.x; j < FF; j += blockDim.x)
            if (row[j]) {
                int pos = g_colptr[j] + atomicAdd(&g_colfill[j], 1);
                if (pos < NNZ_MAX) g_rowidx[pos] = fd;
            }
    }
}

// SDDMM for mask nonzeros (MUST stay fp32: feeds the exact value path)
__global__ void k_mval(const float* __restrict__ Wed) {
    __shared__ float swd[DD];
    int j = blockIdx.x;
    const float* wdrow = g_WdecUpT + (size_t)j * DD;
    for (int i = threadIdx.x; i < DD; i += blockDim.x) swd[i] = wdrow[i];
    __syncthreads();
    int e0 = g_colptr[j];
    int e1 = g_colptr[j + 1];
    if (e1 > NNZ_MAX) e1 = NNZ_MAX;
    int warp = threadIdx.x >> 5, lane = threadIdx.x & 31;
    for (int e = e0 + warp; e < e1; e += (int)blockDim.x / 32) {
        int fd = g_rowidx[e];
        const float* wr = Wed + (size_t)fd * DD;
        float s = 0.f;
#pragma unroll
        for (int t = 0; t < 6; t++) {
            int off = lane * 4 + t * 128;
            float4 a = *(const float4*)(wr + off);
            float4 b = *(const float4*)(swd + off);
            s += a.x * b.x + a.y * b.y + a.z * b.z + a.w * b.w;
        }
        s = warp_red(s);
        if (lane == 0) g_mval[e] = s;
    }
}

// ---------------- bf16 HMMA GEMM (NT), one stage per launch ---------------------
__global__ void __launch_bounds__(256, 2)
k_gemm_mma(const __nv_bfloat16* __restrict__ Ah, const __nv_bfloat16* __restrict__ Bh,
           int z) {
    extern __shared__ char smraw[];
    const uint32_t sbase = smem_u32(smraw);
    __nv_bfloat16* outp = z ? g_buf2 : g_buf1;
    const float* addv = z ? g_add2 : g_add1;
    const int do_relu = (z == 0);
    const int tid = threadIdx.x;
    const int wid = tid >> 5, lane = tid & 31;
    const int bm = blockIdx.y * 128, bn = blockIdx.x * 128;
    const int wm = (wid & 1) * 64, wn = (wid >> 1) * 32;

    const int rr = tid >> 2, q = tid & 3;
    const __nv_bfloat16* srcA = Ah + (size_t)(bm + rr) * DD + q * 8;
    const __nv_bfloat16* srcB = Bh + (size_t)(bn + rr) * DD + q * 8;
    const uint32_t dst0 = sbase + rr * (LDSS * 2) + q * 16;

    float acc[4][4][4];
#pragma unroll
    for (int i = 0; i < 4; i++)
#pragma unroll
        for (int j = 0; j < 4; j++)
#pragma unroll
            for (int k = 0; k < 4; k++) acc[i][j][k] = 0.f;

#pragma unroll
    for (int s = 0; s < STAGES; s++) {
        int k0 = s * KC;
        uint32_t db = dst0 + s * STAGE_B;
        cp16(db, srcA + k0);
        cp16(db + 64 * (LDSS * 2), srcA + k0 + (size_t)64 * DD);
        cp16(db + TILE_B, srcB + k0);
        cp16(db + TILE_B + 64 * (LDSS * 2), srcB + k0 + (size_t)64 * DD);
        asm volatile("cp.async.commit_group;" ::: "memory");
    }

#pragma unroll 1
    for (int c = 0; c < NCHUNK; c++) {
        asm volatile("cp.async.wait_group %0;" :: "n"(STAGES - 1) : "memory");
        __syncthreads();
        int st = c % STAGES;
        uint32_t sA = sbase + st * STAGE_B;
        uint32_t sB = sA + TILE_B;
#pragma unroll
        for (int kk = 0; kk < KC / 16; kk++) {
            uint32_t ah[4][4], bh[4][2];
            int arow = wm + (lane & 15);
            int acol = kk * 16 + (lane >> 4) * 8;
#pragma unroll
            for (int f = 0; f < 4; f++)
                ldm4(ah[f], sA + (uint32_t)((arow + f * 16) * LDSS + acol) * 2);
            int brow = wn + ((lane >> 4) << 3) + (lane & 7);
            int bcol = kk * 16 + ((lane >> 3) & 1) * 8;
#pragma unroll
            for (int g = 0; g < 2; g++) {
                uint32_t r4[4];
                ldm4(r4, sB + (uint32_t)((brow + g * 16) * LDSS + bcol) * 2);
                bh[g * 2][0] = r4[0]; bh[g * 2][1] = r4[1];
                bh[g * 2 + 1][0] = r4[2]; bh[g * 2 + 1][1] = r4[3];
            }
#pragma unroll
            for (int mi = 0; mi < 4; mi++)
#pragma unroll
                for (int ni = 0; ni < 4; ni++)
                    mma_bf16(acc[mi][ni], ah[mi], bh[ni]);
        }
        __syncthreads();
        if (c + STAGES < NCHUNK) {
            int k0 = (c + STAGES) * KC;
            uint32_t db = dst0 + st * STAGE_B;
            cp16(db, srcA + k0);
            cp16(db + 64 * (LDSS * 2), srcA + k0 + (size_t)64 * DD);
            cp16(db + TILE_B, srcB + k0);
            cp16(db + TILE_B + 64 * (LDSS * 2), srcB + k0 + (size_t)64 * DD);
        }
        asm volatile("cp.async.commit_group;" ::: "memory");
    }

#pragma unroll
    for (int ni = 0; ni < 4; ni++) {
        int col = bn + wn + ni * 8 + (lane & 3) * 2;
        float a0 = addv[col], a1 = addv[col + 1];
#pragma unroll
        for (int mi = 0; mi < 4; mi++) {
            int row = bm + wm + mi * 16 + (lane >> 2);
            float v0 = acc[mi][ni][0] + a0;
            float v1 = acc[mi][ni][1] + a1;
            float v2 = acc[mi][ni][2] + a0;
            float v3 = acc[mi][ni][3] + a1;
            if (do_relu) {
                v0 = fmaxf(v0, 0.f); v1 = fmaxf(v1, 0.f);
                v2 = fmaxf(v2, 0.f); v3 = fmaxf(v3, 0.f);
            }
            *(uint32_t*)(outp + (size_t)row * FF + col) =
                bf2u(__floats2bfloat162_rn(v0, v1));
            *(uint32_t*)(outp + (size_t)(row + 8) * FF + col) =
                bf2u(__floats2bfloat162_rn(v2, v3));
        }
    }
}

// exact rank-select among <=CAP candidates; ties -> smallest index
__device__ void rank_select(const int* cidx, const float* cval, int nc,
                            float* oval, int* oidx) {
    for (int c = threadIdx.x; c < nc; c += 512) {
        float v = cval[c];
        int j = cidx[c];
        int rank = 0;
        for (int t = 0; t < nc; t++) {
            float vt = cval[t];
            rank += (vt > v) || (vt == v && cidx[t] < j);
        }
        if (rank < TK) { oidx[rank] = j; oval[rank] = v; }
    }
}

// ---------------- upstream: 2-pass 16-bit radix on bf16 + exact refine ----------
__global__ void __launch_bounds__(512)
k_topk_up_ref(const float* __restrict__ x, const float* __restrict__ W) {
    __shared__ int hist[256];
    __shared__ int misc[8];
    __shared__ int cidx[CAP];
    __shared__ float cval[CAP];
    __shared__ float sx[DD];
    const int tid = threadIdx.x;
    int row = blockIdx.x;
    const unsigned* src32 = (const unsigned*)(g_buf1 + (size_t)row * FF);
    if (tid < 256) hist[tid] = 0;
    if (tid == 0) { misc[1] = TK; misc[4] = 0; }
    __syncthreads();
    // pass 1: top byte of 16-bit key
    for (int w = tid; w < FF / 2; w += 512) {
        unsigned p = src32[w];
        hist_add(hist, key16(p & 0xFFFFu) >> 8, true);
        hist_add(hist, key16(p >> 16) >> 8, true);
    }
    __syncthreads();
    pick_bucket(hist, misc, 1, 2);
    __syncthreads();
    unsigned t1 = (unsigned)misc[0];
    if (tid < 256) hist[tid] = 0;
    __syncthreads();
    // pass 2: low byte among prefix-matching (divergence-safe)
    for (int w = tid; w < FF / 2; w += 512) {
        unsigned p = src32[w];
        unsigned k0 = key16(p & 0xFFFFu), k1 = key16(p >> 16);
        hist_add(hist, k0 & 255u, (k0 >> 8) == t1);
        hist_add(hist, k1 & 255u, (k1 >> 8) == t1);
    }
    __syncthreads();
    pick_bucket(hist, misc, 2, 3);
    __syncthreads();
    float cutoff = val16((t1 << 8) | (unsigned)misc[0]) - MARGIN;
    for (int w = tid; w < FF / 2; w += 512) {
        unsigned p = src32[w];
        float v0 = __uint_as_float((p & 0xFFFFu) << 16);
        float v1 = __uint_as_float(p & 0xFFFF0000u);
        if (v0 >= cutoff) {
            int q = atomicAdd(&misc[4], 1);
            if (q < CAP) cidx[q] = w * 2;
        }
        if (v1 >= cutoff) {
            int q = atomicAdd(&misc[4], 1);
            if (q < CAP) cidx[q] = w * 2 + 1;
        }
    }
    __syncthreads();
    int nc = min(misc[4], CAP);
    const float* xr = x + (size_t)row * DD;
    for (int i = tid; i < DD; i += 512) sx[i] = xr[i];
    __syncthreads();
    int warp = tid >> 5, lane = tid & 31;
    for (int c = warp; c < nc; c += 16) {
        const float* wr = W + (size_t)cidx[c] * DD;
        float s = 0.f;
#pragma unroll
        for (int t = 0; t < 6; t++) {
            int off = lane * 4 + t * 128;
            float4 a = *(const float4*)(wr + off);
            float4 b = *(const float4*)(sx + off);
            s += a.x * b.x + a.y * b.y + a.z * b.z + a.w * b.w;
        }
        s = warp_red(s);
        if (lane == 0) cval[c] = fmaxf(s + g_add1[cidx[c]], 0.f);
    }
    __syncthreads();
    rank_select(cidx, cval, nc, g_upval + row * TK, g_upidx + row * TK);
}

// ---------------- downstream: scatter + 2-pass radix + exact refine -------------
__global__ void __launch_bounds__(512)
k_contrib_topk_ref(const float* __restrict__ x, const float* __restrict__ W) {
    extern __shared__ int fx[];          // FF ints (fixed-point contribs)
    __shared__ int hist[256];
    __shared__ int misc[8];
    __shared__ int cidx[CAP];
    __shared__ float cval[CAP];
    __shared__ float cextra[CAP];
    __shared__ float sx[DD];
    __shared__ int sj[TK];
    __shared__ float sv[TK];
    const int tid = threadIdx.x;
    const int wid = tid >> 5, lane = tid & 31;
    int row = blockIdx.x;
    const unsigned* src32 = (const unsigned*)(g_buf2 + (size_t)row * FF);
    for (int i = tid; i < FF; i += 512) fx[i] = 0;
    if (tid < TK) {
        sj[tid] = g_upidx[row * TK + tid];
        sv[tid] = g_upval[row * TK + tid];
    }
    if (tid < 256) hist[tid] = 0;
    if (tid == 0) { misc[1] = TK; misc[4] = 0; }
    __syncthreads();
    // parallel deterministic scatter (int fixed-point atomics are associative)
#pragma unroll
    for (int s4 = 0; s4 < 4; s4++) {
        int s = wid + s4 * 16;
        int j = sj[s];
        float v = sv[s];
        int e0 = g_colptr[j];
        int e1 = g_colptr[j + 1];
        if (e1 > NNZ_MAX) e1 = NNZ_MAX;
        for (int e = e0 + lane; e < e1; e += 32) {
            int q = __float2int_rn(v * g_mval[e] * FXSCALE);
            atomicAdd(&fx[g_rowidx[e]], q);
        }
    }
    __syncthreads();
    // pass 1
    for (int w = tid; w < FF / 2; w += 512) {
        unsigned p = src32[w];
        float v0 = __uint_as_float((p & 0xFFFFu) << 16) + (float)fx[w * 2] * FXINV;
        float v1 = __uint_as_float(p & 0xFFFF0000u) + (float)fx[w * 2 + 1] * FXINV;
        hist_add(hist, key16((unsigned)__bfloat16_as_ushort(__float2bfloat16_rn(v0))) >> 8, true);
        hist_add(hist, key16((unsigned)__bfloat16_as_ushort(__float2bfloat16_rn(v1))) >> 8, true);
    }
    __syncthreads();
    pick_bucket(hist, misc, 1, 2);
    __syncthreads();
    unsigned t1 = (unsigned)misc[0];
    if (tid < 256) hist[tid] = 0;
    __syncthreads();
    // pass 2 (divergence-safe)
    for (int w = tid; w < FF / 2; w += 512) {
        unsigned p = src32[w];
        float v0 = __uint_as_float((p & 0xFFFFu) << 16) + (float)fx[w * 2] * FXINV;
        float v1 = __uint_as_float(p & 0xFFFF0000u) + (float)fx[w * 2 + 1] * FXINV;
        unsigned k0 = key16((unsigned)__bfloat16_as_ushort(__float2bfloat16_rn(v0)));
        unsigned k1 = key16((unsigned)__bfloat16_as_ushort(__float2bfloat16_rn(v1)));
        hist_add(hist, k0 & 255u, (k0 >> 8) == t1);
        hist_add(hist, k1 & 255u, (k1 >> 8) == t1);
    }
    __syncthreads();
    pick_bucket(hist, misc, 2, 3);
    __syncthreads();
    float cutoff = val16((t1 << 8) | (unsigned)misc[0]) - MARGIN;
    for (int w = tid; w < FF / 2; w += 512) {
        unsigned p = src32[w];
        float v0 = __uint_as_float((p & 0xFFFFu) << 16) + (float)fx[w * 2] * FXINV;
        float v1 = __uint_as_float(p & 0xFFFF0000u) + (float)fx[w * 2 + 1] * FXINV;
        if (v0 >= cutoff) {
            int q = atomicAdd(&misc[4], 1);
            if (q < CAP) cidx[q] = w * 2;
        }
        if (v1 >= cutoff) {
            int q = atomicAdd(&misc[4], 1);
            if (q < CAP) cidx[q] = w * 2 + 1;
        }
    }
    __syncthreads();
    int nc = min(misc[4], CAP);
    for (int c = tid; c < nc; c += 512)
        cextra[c] = (float)fx[cidx[c]] * FXINV;
    __syncthreads();
    const float* xr = x + (size_t)row * DD;
    for (int i = tid; i < DD; i += 512) sx[i] = xr[i];
    __syncthreads();
    for (int c = wid; c < nc; c += 16) {
        const float* wr = W + (size_t)cidx[c] * DD;
        float s = 0.f;
#pragma unroll
        for (int t = 0; t < 6; t++) {
            int off = lane * 4 + t * 128;
            float4 a = *(const float4*)(wr + off);
            float4 b = *(const float4*)(sx + off);
            s += a.x * b.x + a.y * b.y + a.z * b.z + a.w * b.w;
        }
        s = warp_red(s);
        if (lane == 0) cval[c] = s + g_add2[cidx[c]] + cextra[c];
    }
    __syncthreads();
    rank_select(cidx, cval, nc, g_dnval + row * TK, g_dnidx + row * TK);
}

// ---------------- decode --------------------------------------------------------
__global__ void k_decode(const float* __restrict__ bdd, float* __restrict__ out) {
    __shared__ float vj[TK];
    __shared__ int ij[TK];
    int row = blockIdx.x;
    if (threadIdx.x < TK) {
        vj[threadIdx.x] = g_dnval[row * TK + threadIdx.x];
        ij[threadIdx.x] = g_dnidx[row * TK + threadIdx.x];
    }
    __syncthreads();
    int d = threadIdx.x;  // blockDim == 768
    float acc = bdd[d];
#pragma unroll 8
    for (int s = 0; s < TK; s++)
        acc += vj[s] * g_WdecDnT[(size_t)ij[s] * DD + d];
    out[(size_t)row * DD + d] = acc;
}

// ---------------- launch --------------------------------------------------------
extern "C" void kernel_launch(void* const* d_in, const int* in_sizes, int n_in,
                              void* d_out, int out_size) {
    const float* x_up      = (const float*)d_in[0];
    const float* x_resid   = (const float*)d_in[1];
    const float* W_enc_up  = (const float*)d_in[2];
    const float* b_enc_up  = (const float*)d_in[3];
    const float* b_dec_up  = (const float*)d_in[4];
    const float* W_dec_up  = (const float*)d_in[5];
    const float* W_enc_down= (const float*)d_in[6];
    const float* b_enc_down= (const float*)d_in[7];
    const float* b_dec_down= (const float*)d_in[8];
    const float* W_dec_down= (const float*)d_in[9];
    const void*  conn_mask = d_in[10];
    float* out = (float*)d_out;

    __nv_bfloat16 *a1h, *a2h, *b1h, *b2h;
    cudaGetSymbolAddress((void**)&a1h, g_A1h);
    cudaGetSymbolAddress((void**)&a2h, g_A2h);
    cudaGetSymbolAddress((void**)&b1h, g_B1h);
    cudaGetSymbolAddress((void**)&b2h, g_B2h);

    cudaFuncSetAttribute(k_gemm_mma, cudaFuncAttributeMaxDynamicSharedMemorySize, GM_SMEM);
    cudaFuncSetAttribute(k_contrib_topk_ref, cudaFuncAttributeMaxDynamicSharedMemorySize, FF * 4);

    const int NCVT = (2 * MR * DD / 4 + 2 * FF * DD / 4) / 256;
    // GEMM at launches 4-5 so the ncu window (-s 5 -c 1) lands on it
    k_init<<<48, 256>>>();
    k_cvt_all<<<NCVT, 256>>>(x_up, x_resid, W_enc_up, W_enc_down, a1h, a2h, b1h, b2h);
    k_addvec<<<1536, 256>>>(W_enc_up, b_enc_up, b_dec_up, W_enc_down, b_enc_down);
    k_gemm_mma<<<dim3(96, 32), 256, GM_SMEM>>>(a1h, b1h, 0);
    k_gemm_mma<<<dim3(96, 32), 256, GM_SMEM>>>(a2h, b2h, 1);
    k_detect<<<1024, 256>>>((const unsigned*)conn_mask);
    k_transpose<<<dim3(384, 24), dim3(32, 8)>>>(W_dec_up, 0);
    k_transpose<<<dim3(384, 24), dim3(32, 8)>>>(W_dec_down, 1);
    k_maskcount<<<FF, 256>>>(conn_mask);
    k_scan<<<1, 1024>>>();
    k_maskfill<<<FF, 256>>>(conn_mask);
    k_mval<<<FF, 256>>>(W_enc_down);
    k_topk_up_ref<<<MR, 512>>>(x_up, W_enc_up);
    k_contrib_topk_ref<<<MR, 512, FF * 4>>>(x_resid, W_enc_down);
    k_decode<<<MR, 768>>>(b_dec_down, out);
}